// round 9
// baseline (speedup 1.0000x reference)
#include <cuda_runtime.h>
#include <math.h>

#define TPB 128
#define ROWS_PER_BLOCK 256

// ---------------- constant bank ----------------
// [0     : 7680)  emb cols 24..55  [j*32 + (c-24)]  (level0 emb || base_ctrl)
// [7680  : 7920)  kbc [j]  = bc[j] + 2*C
// [7920  : 10624) rw1 [c*52 + k]
#define EMBC_OFF 0
#define KBC_OFF  7680
#define RW1_OFF  7920
#define CTAB_N   10624
__constant__ __align__(16) float c_tab[CTAB_N];
__device__ __align__(16) float g_stage[CTAB_N];
__device__ __align__(16) float g_roots[240 * 8];

typedef unsigned long long u64;

__device__ __forceinline__ u64 pk(float x, float y) {
    u64 r; asm("mov.b64 %0,{%1,%2};" : "=l"(r) : "f"(x), "f"(y)); return r;
}
__device__ __forceinline__ void upk(float& x, float& y, u64 v) {
    asm("mov.b64 {%0,%1},%2;" : "=f"(x), "=f"(y) : "l"(v));
}
__device__ __forceinline__ u64 f2fma(u64 a, u64 b, u64 c) {
    u64 d; asm("fma.rn.f32x2 %0,%1,%2,%3;" : "=l"(d) : "l"(a), "l"(b), "l"(c)); return d;
}
__device__ __forceinline__ u64 f2mul(u64 a, u64 b) {
    u64 d; asm("mul.rn.f32x2 %0,%1,%2;" : "=l"(d) : "l"(a), "l"(b)); return d;
}
__device__ __forceinline__ u64 f2add(u64 a, u64 b) {
    u64 d; asm("add.rn.f32x2 %0,%1,%2;" : "=l"(d) : "l"(a), "l"(b)); return d;
}
__device__ __forceinline__ float ex2a(float x) {
    float y; asm("ex2.approx.ftz.f32 %0,%1;" : "=f"(y) : "f"(x)); return y;
}

// Combined prep: roots + constant-bank stage.
__global__ void prep_kernel(const float* __restrict__ le,
                            const float* __restrict__ bctl,
                            const float* __restrict__ bc,
                            const float* __restrict__ rw1) {
    const float C = 1.0201941611100342f;   // log2(e)/sqrt(2)
    int i = blockIdx.x * blockDim.x + threadIdx.x;
    if (i < 240) {
        float v[8];
#pragma unroll
        for (int k = 0; k < 8; k++) v[k] = 0.f;
        if (i < 112) {
            int p = i >> 2, sb = i & 3;
            int a = 0, rem = p;
            while (rem >= 7 - a) { rem -= (7 - a); a++; }
            int b = a + 1 + rem;
            v[a] = (sb & 2) ? -1.f : 1.f;
            v[b] = (sb & 1) ? -1.f : 1.f;
        } else {
            int b = (i - 112) << 1;
            if (__popc(b) & 1) b |= 1;
#pragma unroll
            for (int k = 0; k < 8; k++) v[k] = ((b >> k) & 1) ? -0.5f : 0.5f;
        }
#pragma unroll
        for (int k = 0; k < 8; k++) g_roots[i * 8 + k] = v[k];
    }
    if (i < CTAB_N) {
        float v;
        if (i < KBC_OFF) {
            int j = i / 32, c = i - j * 32 + 24;
            v = (c < 52) ? le[j * 52 + c] : bctl[j * 4 + (c - 52)];
        } else if (i < RW1_OFF) {
            v = bc[i - KBC_OFF] + 2.0f * C;
        } else {
            v = rw1[i - RW1_OFF];
        }
        g_stage[i] = v;
    }
}

__device__ __forceinline__ float gelu_exact(float x) {
    return 0.5f * x * (1.0f + erff(x * 0.70710678118654752f));
}

// Analytic nearest-E8-root: returns reference enumeration index, subtracts root*s in place.
__device__ __forceinline__ int decode_step(float res[8], float s) {
    float a[8];
#pragma unroll
    for (int k = 0; k < 8; k++) a[k] = fabsf(res[k]);
    int m1 = 0; float v1 = a[0];
#pragma unroll
    for (int k = 1; k < 8; k++) if (a[k] > v1) { v1 = a[k]; m1 = k; }
    int m2 = -1; float v2 = -1.f;
#pragma unroll
    for (int k = 0; k < 8; k++) if (k != m1 && a[k] > v2) { v2 = a[k]; m2 = k; }
    float valA = v1 + v2;
    float sum = 0.f;
#pragma unroll
    for (int k = 0; k < 8; k++) sum += a[k];
    int mask = 0;
#pragma unroll
    for (int k = 0; k < 8; k++) mask |= (res[k] < 0.f) ? (1 << k) : 0;
    int km = 0; float vm = a[0];
#pragma unroll
    for (int k = 1; k < 8; k++) if (a[k] < vm) { vm = a[k]; km = k; }
    int par = __popc(mask) & 1;
    float valB = 0.5f * sum - (par ? vm : 0.f);
    int idx;
    if (valA >= valB) {            // tie -> type A (lower enumeration index)
        int i = (m1 < m2) ? m1 : m2, jj = (m1 < m2) ? m2 : m1;
        int bi = (res[i] < 0.f) ? 1 : 0, bj = (res[jj] < 0.f) ? 1 : 0;
        idx = (7 * i - (i * (i - 1)) / 2 + (jj - i - 1)) * 4 + bi * 2 + bj;
        float di = bi ? -s : s, dj = bj ? -s : s;
#pragma unroll
        for (int k = 0; k < 8; k++) {
            if (k == i)  res[k] -= di;
            if (k == jj) res[k] -= dj;
        }
    } else {
        int bits = par ? (mask ^ (1 << km)) : mask;
        idx = 112 + (bits >> 1);
        float hs = 0.5f * s;
#pragma unroll
        for (int k = 0; k < 8; k++) res[k] -= ((bits >> k) & 1) ? -hs : hs;
    }
    return idx;
}

// dot + exp for root j (both rows) — the "next-iteration" stage of the pipeline.
__device__ __forceinline__ void dot_e(int j, const float* rootsS,
                                      const u64 qp0[4], const u64 qp1[4],
                                      float& e0, float& e1) {
    const float C = 1.0201941611100342f;
    const u64* rp = reinterpret_cast<const u64*>(&rootsS[j * 8]);
    u64 rr0 = rp[0], rr1 = rp[1], rr2 = rp[2], rr3 = rp[3];
    u64 d0 = f2mul(qp0[0], rr0);
    d0 = f2fma(qp0[1], rr1, d0); d0 = f2fma(qp0[2], rr2, d0); d0 = f2fma(qp0[3], rr3, d0);
    u64 d1 = f2mul(qp1[0], rr0);
    d1 = f2fma(qp1[1], rr1, d1); d1 = f2fma(qp1[2], rr2, d1); d1 = f2fma(qp1[3], rr3, d1);
    float dl, dh; upk(dl, dh, d0); float dot0 = dl + dh;
    float el, eh; upk(el, eh, d1); float dot1 = el + eh;
    float kbc = c_tab[KBC_OFF + j];
    e0 = ex2a(fmaf(dot0, C, -kbc));
    e1 = ex2a(fmaf(dot1, C, -kbc));
}

// table accumulate for root j with given weights (both rows).
// cols 0..23 smem (6 LDS.128), cols 24..55 const (8 LDC.128).
__device__ __forceinline__ void accum_tab(int j, float e0, float e1,
                                          u64 acc0[28], u64 acc1[28],
                                          float& S0, float& S1,
                                          const float* embS24) {
    S0 += e0; S1 += e1;
    u64 e0b = pk(e0, e0), e1b = pk(e1, e1);
    const ulonglong2* es = reinterpret_cast<const ulonglong2*>(&embS24[j * 24]);
#pragma unroll
    for (int k = 0; k < 6; k++) {
        ulonglong2 w = es[k];
        acc0[2 * k]     = f2fma(e0b, w.x, acc0[2 * k]);
        acc0[2 * k + 1] = f2fma(e0b, w.y, acc0[2 * k + 1]);
        acc1[2 * k]     = f2fma(e1b, w.x, acc1[2 * k]);
        acc1[2 * k + 1] = f2fma(e1b, w.y, acc1[2 * k + 1]);
    }
    const ulonglong2* ec = reinterpret_cast<const ulonglong2*>(&c_tab[EMBC_OFF + j * 32]);
#pragma unroll
    for (int k = 0; k < 8; k++) {
        ulonglong2 w = ec[k];
        acc0[12 + 2 * k]     = f2fma(e0b, w.x, acc0[12 + 2 * k]);
        acc0[12 + 2 * k + 1] = f2fma(e0b, w.y, acc0[12 + 2 * k + 1]);
        acc1[12 + 2 * k]     = f2fma(e1b, w.x, acc1[12 + 2 * k]);
        acc1[12 + 2 * k + 1] = f2fma(e1b, w.y, acc1[12 + 2 * k + 1]);
    }
}

// Gated refine MLP for one row (acc[28] u64 = 56 floats, cols 0..51 refined).
// Layer-1 weights from constant bank (LDC), layer-2 from smem (LDS) — balanced ports.
__device__ __forceinline__ void refine_row(u64 acc[28],
                                           const float* rw2TS, const float* rb1S,
                                           const float* rb2S, u64 gateb) {
    u64 r2a[26];
#pragma unroll
    for (int k = 0; k < 26; k++) r2a[k] = 0ull;
#pragma unroll 2
    for (int c = 0; c < 52; c++) {
        u64 p = pk(rb1S[c], 0.f);
        const ulonglong2* wr = reinterpret_cast<const ulonglong2*>(&c_tab[RW1_OFF + c * 52]);
#pragma unroll
        for (int k = 0; k < 13; k++) {
            ulonglong2 w = wr[k];
            p = f2fma(acc[2 * k], w.x, p);
            p = f2fma(acc[2 * k + 1], w.y, p);
        }
        float pl, ph; upk(pl, ph, p);
        float gv = gelu_exact(pl + ph);
        u64 gvb = pk(gv, gv);
        const ulonglong2* w2r = reinterpret_cast<const ulonglong2*>(rw2TS + c * 52);
#pragma unroll
        for (int k = 0; k < 13; k++) {
            ulonglong2 w = w2r[k];
            r2a[2 * k]     = f2fma(gvb, w.x, r2a[2 * k]);
            r2a[2 * k + 1] = f2fma(gvb, w.y, r2a[2 * k + 1]);
        }
    }
    const u64* rb2p = reinterpret_cast<const u64*>(rb2S);
#pragma unroll
    for (int k = 0; k < 26; k++)
        acc[k] = f2fma(gateb, f2add(r2a[k], rb2p[k]), acc[k]);
}

__global__ __launch_bounds__(TPB, 3) void rcpl_kernel(
    const float* __restrict__ obs,   const float* __restrict__ w1, const float* __restrict__ b1,
    const float* __restrict__ w2,    const float* __restrict__ b2,
    const float* __restrict__ le,    const float* __restrict__ rctl,
    const float* __restrict__ ld,
    const float* __restrict__ rb1,
    const float* __restrict__ rw2,   const float* __restrict__ rb2,
    const float* __restrict__ rgate, float* __restrict__ out, int B)
{
    __shared__ __align__(16) float rootsS[1920];   // [j*8+k]
    __shared__ __align__(16) float embS24[5760];   // [j*24+c] emb cols 0..23
    __shared__ __align__(16) float rw2TS[2704];    // [c*52+k2] (transposed)
    __shared__ __align__(16) float w1S[448];       // [l*14+k]
    __shared__ __align__(16) float w2TS[256];      // [l*8+j]  (transposed)
    __shared__ float b1S[32];
    __shared__ float b2S[8];
    __shared__ __align__(16) float rb2S[52];
    __shared__ float rb1S[52];
    // ~45 KB static (< 48 KB), 3 CTAs fit the 228 KB carveout.

    const int t = threadIdx.x;

    for (int i = t; i < 1920; i += TPB) rootsS[i] = g_roots[i];
    for (int i = t; i < 5760; i += TPB) { int j = i / 24, c = i - j * 24; embS24[i] = le[j * 52 + c]; }
    for (int i = t; i < 2704; i += TPB) { int c = i / 52, k = i - c * 52; rw2TS[i] = rw2[k * 52 + c]; }
    for (int i = t; i < 448;  i += TPB) w1S[i] = w1[i];
    for (int i = t; i < 256;  i += TPB) { int l = i >> 3, j = i & 7; w2TS[i] = w2[j * 32 + l]; }
    for (int i = t; i < 32;   i += TPB) b1S[i] = b1[i];
    for (int i = t; i < 8;    i += TPB) b2S[i] = b2[i];
    for (int i = t; i < 52;   i += TPB) { rb1S[i] = rb1[i]; rb2S[i] = rb2[i]; }
    __syncthreads();

    int r0 = blockIdx.x * ROWS_PER_BLOCK + t;
    if (r0 >= B) return;
    int r1 = r0 + TPB;
    bool has1 = (r1 < B);
    int r1c = has1 ? r1 : r0;

    // ---------------- projection: 14 -> 32 -> 8 for both rows ----------------
    float x0[14], x1[14];
    {
        const float2* p0 = reinterpret_cast<const float2*>(obs + (size_t)r0 * 14);
        const float2* p1 = reinterpret_cast<const float2*>(obs + (size_t)r1c * 14);
#pragma unroll
        for (int k = 0; k < 7; k++) {
            float2 v0 = p0[k], v1 = p1[k];
            x0[2 * k] = v0.x; x0[2 * k + 1] = v0.y;
            x1[2 * k] = v1.x; x1[2 * k + 1] = v1.y;
        }
    }
    float q0[8], q1[8];
#pragma unroll
    for (int j = 0; j < 8; j++) { q0[j] = b2S[j]; q1[j] = b2S[j]; }
#pragma unroll 2
    for (int l = 0; l < 32; l++) {
        float h0 = b1S[l], h1 = b1S[l];
        const float2* wr = reinterpret_cast<const float2*>(&w1S[l * 14]);
#pragma unroll
        for (int k = 0; k < 7; k++) {
            float2 w = wr[k];
            h0 = fmaf(x0[2 * k], w.x, h0); h0 = fmaf(x0[2 * k + 1], w.y, h0);
            h1 = fmaf(x1[2 * k], w.x, h1); h1 = fmaf(x1[2 * k + 1], w.y, h1);
        }
        float g0 = gelu_exact(h0), g1 = gelu_exact(h1);
        const float4* wt = reinterpret_cast<const float4*>(&w2TS[l * 8]);
        float4 u0 = wt[0], u1 = wt[1];
        q0[0] = fmaf(g0, u0.x, q0[0]); q0[1] = fmaf(g0, u0.y, q0[1]);
        q0[2] = fmaf(g0, u0.z, q0[2]); q0[3] = fmaf(g0, u0.w, q0[3]);
        q0[4] = fmaf(g0, u1.x, q0[4]); q0[5] = fmaf(g0, u1.y, q0[5]);
        q0[6] = fmaf(g0, u1.z, q0[6]); q0[7] = fmaf(g0, u1.w, q0[7]);
        q1[0] = fmaf(g1, u0.x, q1[0]); q1[1] = fmaf(g1, u0.y, q1[1]);
        q1[2] = fmaf(g1, u0.z, q1[2]); q1[3] = fmaf(g1, u0.w, q1[3]);
        q1[4] = fmaf(g1, u1.x, q1[4]); q1[5] = fmaf(g1, u1.y, q1[5]);
        q1[6] = fmaf(g1, u1.z, q1[6]); q1[7] = fmaf(g1, u1.w, q1[7]);
    }
    {
        float n0 = 0.f, n1 = 0.f;
#pragma unroll
        for (int j = 0; j < 8; j++) { n0 = fmaf(q0[j], q0[j], n0); n1 = fmaf(q1[j], q1[j], n1); }
        float s0 = 1.4142135623730951f / fmaxf(sqrtf(n0), 1e-12f);
        float s1 = 1.4142135623730951f / fmaxf(sqrtf(n1), 1e-12f);
#pragma unroll
        for (int j = 0; j < 8; j++) { q0[j] *= s0; q1[j] *= s1; }
    }

    u64 qp0[4], qp1[4];
#pragma unroll
    for (int k = 0; k < 4; k++) { qp0[k] = pk(q0[2 * k], q0[2 * k + 1]); qp1[k] = pk(q1[2 * k], q1[2 * k + 1]); }

    // ------- fused 240-root pass, software-pipelined: e(j+1) computed before acc(j) -------
    u64 acc0[28], acc1[28];
#pragma unroll
    for (int k = 0; k < 28; k++) { acc0[k] = 0ull; acc1[k] = 0ull; }
    float S0 = 0.f, S1 = 0.f;
    float e0c, e1c;
    dot_e(0, rootsS, qp0, qp1, e0c, e1c);
#pragma unroll 2
    for (int j = 0; j < 239; j++) {
        float e0n, e1n;
        dot_e(j + 1, rootsS, qp0, qp1, e0n, e1n);      // next iteration (independent)
        accum_tab(j, e0c, e1c, acc0, acc1, S0, S1, embS24);
        e0c = e0n; e1c = e1n;
    }
    accum_tab(239, e0c, e1c, acc0, acc1, S0, S1, embS24);
    {
        float i0 = 1.0f / S0, i1 = 1.0f / S1;
        u64 iv0 = pk(i0, i0), iv1 = pk(i1, i1);
#pragma unroll
        for (int k = 0; k < 28; k++) { acc0[k] = f2mul(acc0[k], iv0); acc1[k] = f2mul(acc1[k], iv1); }
    }

    // ------- residual E8 quantization: analytic decode fused with gathers -------
    float invd = expf(-ld[0]);
    {
        float res0[8], res1[8];
#pragma unroll
        for (int k = 0; k < 4; k++) {
            upk(res0[2 * k], res0[2 * k + 1], qp0[k]);
            upk(res1[2 * k], res1[2 * k + 1], qp1[k]);
        }
        float s = 2.f, gg = 1.f;
#pragma unroll
        for (int lev = 0; lev < 8; lev++) {
            int idx0 = decode_step(res0, s);
            int idx1 = decode_step(res1, s);
            if (lev > 0) {
                u64 gb = pk(gg, gg);
                const ulonglong2* e0p = reinterpret_cast<const ulonglong2*>(le + ((size_t)lev * 240 + idx0) * 52);
                const ulonglong2* e1p = reinterpret_cast<const ulonglong2*>(le + ((size_t)lev * 240 + idx1) * 52);
#pragma unroll
                for (int k = 0; k < 13; k++) {
                    ulonglong2 w0 = __ldg(&e0p[k]), w1v = __ldg(&e1p[k]);
                    acc0[2 * k]     = f2fma(gb, w0.x, acc0[2 * k]);
                    acc0[2 * k + 1] = f2fma(gb, w0.y, acc0[2 * k + 1]);
                    acc1[2 * k]     = f2fma(gb, w1v.x, acc1[2 * k]);
                    acc1[2 * k + 1] = f2fma(gb, w1v.y, acc1[2 * k + 1]);
                }
                ulonglong2 c0 = __ldg(reinterpret_cast<const ulonglong2*>(rctl + ((size_t)(lev - 1) * 240 + idx0) * 4));
                ulonglong2 c1 = __ldg(reinterpret_cast<const ulonglong2*>(rctl + ((size_t)(lev - 1) * 240 + idx1) * 4));
                acc0[26] = f2fma(gb, c0.x, acc0[26]); acc0[27] = f2fma(gb, c0.y, acc0[27]);
                acc1[26] = f2fma(gb, c1.x, acc1[26]); acc1[27] = f2fma(gb, c1.y, acc1[27]);
            }
            s *= invd; gg *= invd;
        }
    }

    // ------- stash row1 pre-refine acc to out (register relief), refine row0 -------
    float4* op1 = reinterpret_cast<float4*>(out + (size_t)r1c * 56);
    if (has1) {
#pragma unroll
        for (int c4 = 0; c4 < 14; c4++) {
            float4 v;
            upk(v.x, v.y, acc1[2 * c4]); upk(v.z, v.w, acc1[2 * c4 + 1]);
            op1[c4] = v;
        }
    }

    float gate = 1.0f / (1.0f + expf(-rgate[0]));
    u64 gateb = pk(gate, gate);

    refine_row(acc0, rw2TS, rb1S, rb2S, gateb);
    {
        float4* op = reinterpret_cast<float4*>(out + (size_t)r0 * 56);
#pragma unroll
        for (int c4 = 0; c4 < 14; c4++) {
            float4 v;
            upk(v.x, v.y, acc0[2 * c4]); upk(v.z, v.w, acc0[2 * c4 + 1]);
            op[c4] = v;
        }
    }

    if (has1) {
#pragma unroll
        for (int c4 = 0; c4 < 14; c4++) {
            float4 v = op1[c4];
            acc1[2 * c4] = pk(v.x, v.y); acc1[2 * c4 + 1] = pk(v.z, v.w);
        }
        refine_row(acc1, rw2TS, rb1S, rb2S, gateb);
#pragma unroll
        for (int c4 = 0; c4 < 14; c4++) {
            float4 v;
            upk(v.x, v.y, acc1[2 * c4]); upk(v.z, v.w, acc1[2 * c4 + 1]);
            op1[c4] = v;
        }
    }
}

extern "C" void kernel_launch(void* const* d_in, const int* in_sizes, int n_in,
                              void* d_out, int out_size) {
    const float* obs   = (const float*)d_in[0];
    const float* w1    = (const float*)d_in[1];
    const float* b1    = (const float*)d_in[2];
    const float* w2    = (const float*)d_in[3];
    const float* b2    = (const float*)d_in[4];
    const float* le    = (const float*)d_in[5];
    const float* bctl  = (const float*)d_in[6];
    const float* rctl  = (const float*)d_in[7];
    const float* bc    = (const float*)d_in[8];
    const float* ld    = (const float*)d_in[9];
    const float* rw1   = (const float*)d_in[10];
    const float* rb1   = (const float*)d_in[11];
    const float* rw2   = (const float*)d_in[12];
    const float* rb2   = (const float*)d_in[13];
    const float* rgate = (const float*)d_in[14];
    float* out = (float*)d_out;

    int B = in_sizes[0] / 14;

    prep_kernel<<<(CTAB_N + 255) / 256, 256>>>(le, bctl, bc, rw1);

    void* c_addr = nullptr;
    void* s_addr = nullptr;
    cudaGetSymbolAddress(&c_addr, c_tab);
    cudaGetSymbolAddress(&s_addr, g_stage);
    cudaMemcpyAsync(c_addr, s_addr, CTAB_N * sizeof(float), cudaMemcpyDeviceToDevice, 0);

    int blocks = (B + ROWS_PER_BLOCK - 1) / ROWS_PER_BLOCK;
    rcpl_kernel<<<blocks, TPB>>>(
        obs, w1, b1, w2, b2, le, rctl, ld, rb1, rw2, rb2, rgate, out, B);
}

// round 11
// speedup vs baseline: 1.3461x; 1.3461x over previous
#include <cuda_runtime.h>
#include <cuda_fp16.h>
#include <math.h>

#define TPB 128

// ---------------- constant bank: refine layer-1 weights only ----------------
#define CTAB_N 2704
__constant__ __align__(16) float c_tab[CTAB_N];   // rw1 [c*52 + k]
__device__ __align__(16) float g_stage[CTAB_N];
__device__ __align__(16) float g_roots[240 * 8];

// ---------------- dynamic smem layout (byte offsets from 16B-aligned base) ----------------
#define OFF_WT    0        // fp16 W [n=64][k=248 pad]  = 31744 B   (aliased by OUTS after MMA)
#define OFF_OUTS  0        // fp32 D [row=128][60 pad]  = 30720 B
#define WT_STRIDE 248
#define OFF_ROOTS 31744    // 1920 f
#define OFF_KBC   39424    // 240 f   (bc[j] + 2C)
#define OFF_RW2T  40384    // 2704 f  rw2 transposed [c*52+k]
#define OFF_W1    51200    // 448 f
#define OFF_W2T   52992    // 256 f
#define OFF_B1    54016    // 32 f
#define OFF_B2    54144    // 8 f
#define OFF_RB1   54176    // 52 f
#define OFF_RB2   54384    // 52 f
#define OFF_QS    54592    // 128 rows x 10 f (8 used, pad 10) = 5120 B
#define SMEM_REQ  59712

typedef unsigned long long u64;

// ---------------- PTX helpers ----------------
__device__ __forceinline__ u64 pk(float x, float y) {
    u64 r; asm("mov.b64 %0,{%1,%2};" : "=l"(r) : "f"(x), "f"(y)); return r;
}
__device__ __forceinline__ void upk(float& x, float& y, u64 v) {
    asm("mov.b64 {%0,%1},%2;" : "=f"(x), "=f"(y) : "l"(v));
}
__device__ __forceinline__ u64 f2fma(u64 a, u64 b, u64 c) {
    u64 d; asm("fma.rn.f32x2 %0,%1,%2,%3;" : "=l"(d) : "l"(a), "l"(b), "l"(c)); return d;
}
__device__ __forceinline__ u64 f2mul(u64 a, u64 b) {
    u64 d; asm("mul.rn.f32x2 %0,%1,%2;" : "=l"(d) : "l"(a), "l"(b)); return d;
}
__device__ __forceinline__ u64 f2add(u64 a, u64 b) {
    u64 d; asm("add.rn.f32x2 %0,%1,%2;" : "=l"(d) : "l"(a), "l"(b)); return d;
}
__device__ __forceinline__ float ex2a(float x) {
    float y; asm("ex2.approx.ftz.f32 %0,%1;" : "=f"(y) : "f"(x)); return y;
}
// f16x2 with `lo` in the low half (smaller k index first)
__device__ __forceinline__ unsigned pk16(float lo, float hi) {
    unsigned d; asm("cvt.rn.f16x2.f32 %0,%1,%2;" : "=r"(d) : "f"(hi), "f"(lo)); return d;
}
// m16n8k16 row.col f16xf16 -> f32
__device__ __forceinline__ void mma16816(float* c, const unsigned a[4], unsigned b0, unsigned b1) {
    asm volatile("mma.sync.aligned.m16n8k16.row.col.f32.f16.f16.f32 "
        "{%0,%1,%2,%3}, {%4,%5,%6,%7}, {%8,%9}, {%0,%1,%2,%3};"
        : "+f"(c[0]), "+f"(c[1]), "+f"(c[2]), "+f"(c[3])
        : "r"(a[0]), "r"(a[1]), "r"(a[2]), "r"(a[3]), "r"(b0), "r"(b1));
}

// ---------------- prep: roots + const-bank stage ----------------
__global__ void prep_kernel(const float* __restrict__ rw1) {
    int i = blockIdx.x * blockDim.x + threadIdx.x;
    if (i < 240) {
        float v[8];
#pragma unroll
        for (int k = 0; k < 8; k++) v[k] = 0.f;
        if (i < 112) {
            int p = i >> 2, sb = i & 3;
            int a = 0, rem = p;
            while (rem >= 7 - a) { rem -= (7 - a); a++; }
            int b = a + 1 + rem;
            v[a] = (sb & 2) ? -1.f : 1.f;
            v[b] = (sb & 1) ? -1.f : 1.f;
        } else {
            int b = (i - 112) << 1;
            if (__popc(b) & 1) b |= 1;
#pragma unroll
            for (int k = 0; k < 8; k++) v[k] = ((b >> k) & 1) ? -0.5f : 0.5f;
        }
#pragma unroll
        for (int k = 0; k < 8; k++) g_roots[i * 8 + k] = v[k];
    }
    if (i < CTAB_N) g_stage[i] = rw1[i];
}

__device__ __forceinline__ float gelu_exact(float x) {
    return 0.5f * x * (1.0f + erff(x * 0.70710678118654752f));
}

// Analytic nearest-E8-root decode (reference enumeration index), subtracts root*s in place.
__device__ __forceinline__ int decode_step(float res[8], float s) {
    float a[8];
#pragma unroll
    for (int k = 0; k < 8; k++) a[k] = fabsf(res[k]);
    int m1 = 0; float v1 = a[0];
#pragma unroll
    for (int k = 1; k < 8; k++) if (a[k] > v1) { v1 = a[k]; m1 = k; }
    int m2 = -1; float v2 = -1.f;
#pragma unroll
    for (int k = 0; k < 8; k++) if (k != m1 && a[k] > v2) { v2 = a[k]; m2 = k; }
    float valA = v1 + v2;
    float sum = 0.f;
#pragma unroll
    for (int k = 0; k < 8; k++) sum += a[k];
    int mask = 0;
#pragma unroll
    for (int k = 0; k < 8; k++) mask |= (res[k] < 0.f) ? (1 << k) : 0;
    int km = 0; float vm = a[0];
#pragma unroll
    for (int k = 1; k < 8; k++) if (a[k] < vm) { vm = a[k]; km = k; }
    int par = __popc(mask) & 1;
    float valB = 0.5f * sum - (par ? vm : 0.f);
    int idx;
    if (valA >= valB) {
        int i = (m1 < m2) ? m1 : m2, jj = (m1 < m2) ? m2 : m1;
        int bi = (res[i] < 0.f) ? 1 : 0, bj = (res[jj] < 0.f) ? 1 : 0;
        idx = (7 * i - (i * (i - 1)) / 2 + (jj - i - 1)) * 4 + bi * 2 + bj;
        float di = bi ? -s : s, dj = bj ? -s : s;
#pragma unroll
        for (int k = 0; k < 8; k++) {
            if (k == i)  res[k] -= di;
            if (k == jj) res[k] -= dj;
        }
    } else {
        int bits = par ? (mask ^ (1 << km)) : mask;
        idx = 112 + (bits >> 1);
        float hs = 0.5f * s;
#pragma unroll
        for (int k = 0; k < 8; k++) res[k] -= ((bits >> k) & 1) ? -hs : hs;
    }
    return idx;
}

__global__ __launch_bounds__(TPB, 3) void rcpl_kernel(
    const float* __restrict__ obs,   const float* __restrict__ w1, const float* __restrict__ b1,
    const float* __restrict__ w2,    const float* __restrict__ b2,
    const float* __restrict__ le,    const float* __restrict__ bctl,
    const float* __restrict__ rctl,  const float* __restrict__ bc,
    const float* __restrict__ ld,
    const float* __restrict__ rb1,
    const float* __restrict__ rw2,   const float* __restrict__ rb2,
    const float* __restrict__ rgate, float* __restrict__ out, int B)
{
    extern __shared__ __align__(16) char sm[];
    __half*  Wt     = reinterpret_cast<__half*>(sm + OFF_WT);
    float*   outS   = reinterpret_cast<float*>(sm + OFF_OUTS);
    float*   rootsS = reinterpret_cast<float*>(sm + OFF_ROOTS);
    float*   kbcS   = reinterpret_cast<float*>(sm + OFF_KBC);
    float*   rw2TS  = reinterpret_cast<float*>(sm + OFF_RW2T);
    float*   w1S    = reinterpret_cast<float*>(sm + OFF_W1);
    float*   w2TS   = reinterpret_cast<float*>(sm + OFF_W2T);
    float*   b1S    = reinterpret_cast<float*>(sm + OFF_B1);
    float*   b2S    = reinterpret_cast<float*>(sm + OFF_B2);
    float*   rb1S   = reinterpret_cast<float*>(sm + OFF_RB1);
    float*   rb2S   = reinterpret_cast<float*>(sm + OFF_RB2);
    float*   qS     = reinterpret_cast<float*>(sm + OFF_QS);

    const float C = 1.0201941611100342f;   // log2(e)/sqrt(2)
    const int tid = threadIdx.x;

    // zero full W-table first (pad rows/cols must be 0)
    {
        unsigned* wz = reinterpret_cast<unsigned*>(Wt);
        for (int i = tid; i < (64 * WT_STRIDE) / 2; i += TPB) wz[i] = 0u;
    }
    __syncthreads();
    // fills
    for (int i = tid; i < 240 * 56; i += TPB) {
        int j = i / 56, c = i - j * 56;
        float v = (c < 52) ? le[j * 52 + c] : bctl[j * 4 + (c - 52)];
        Wt[c * WT_STRIDE + j] = __float2half_rn(v);
    }
    for (int i = tid; i < 1920; i += TPB) rootsS[i] = g_roots[i];
    for (int i = tid; i < 240;  i += TPB) kbcS[i] = bc[i] + 2.0f * C;
    for (int i = tid; i < 2704; i += TPB) { int c = i / 52, k = i - c * 52; rw2TS[i] = rw2[k * 52 + c]; }
    for (int i = tid; i < 448;  i += TPB) w1S[i] = w1[i];
    for (int i = tid; i < 256;  i += TPB) { int l = i >> 3, j = i & 7; w2TS[i] = w2[j * 32 + l]; }
    for (int i = tid; i < 32;   i += TPB) b1S[i] = b1[i];
    for (int i = tid; i < 8;    i += TPB) b2S[i] = b2[i];
    for (int i = tid; i < 52;   i += TPB) { rb1S[i] = rb1[i]; rb2S[i] = rb2[i]; }
    __syncthreads();

    int grow = blockIdx.x * TPB + tid;
    int row = (grow < B) ? grow : (B - 1);

    // ---------------- projection 14 -> 32 -> 8 (own row) -> qS ----------------
    {
        float x[14];
        const float2* p0 = reinterpret_cast<const float2*>(obs + (size_t)row * 14);
#pragma unroll
        for (int k = 0; k < 7; k++) { float2 v = p0[k]; x[2 * k] = v.x; x[2 * k + 1] = v.y; }
        float q[8];
#pragma unroll
        for (int j = 0; j < 8; j++) q[j] = b2S[j];
#pragma unroll 2
        for (int l = 0; l < 32; l++) {
            float h = b1S[l];
            const float2* wr = reinterpret_cast<const float2*>(&w1S[l * 14]);
#pragma unroll
            for (int k = 0; k < 7; k++) { float2 w = wr[k]; h = fmaf(x[2 * k], w.x, h); h = fmaf(x[2 * k + 1], w.y, h); }
            float g = gelu_exact(h);
            const float4* wt = reinterpret_cast<const float4*>(&w2TS[l * 8]);
            float4 u0 = wt[0], u1 = wt[1];
            q[0] = fmaf(g, u0.x, q[0]); q[1] = fmaf(g, u0.y, q[1]);
            q[2] = fmaf(g, u0.z, q[2]); q[3] = fmaf(g, u0.w, q[3]);
            q[4] = fmaf(g, u1.x, q[4]); q[5] = fmaf(g, u1.y, q[5]);
            q[6] = fmaf(g, u1.z, q[6]); q[7] = fmaf(g, u1.w, q[7]);
        }
        float n2 = 0.f;
#pragma unroll
        for (int j = 0; j < 8; j++) n2 = fmaf(q[j], q[j], n2);
        float sc = 1.4142135623730951f / fmaxf(sqrtf(n2), 1e-12f);
#pragma unroll
        for (int j = 0; j < 8; j++) qS[tid * 10 + j] = q[j] * sc;
    }
    __syncthreads();

    // ---------------- dot/exp -> A fragments + inline HMMA ----------------
    const int wb = (tid >> 5) << 5;          // warp's 32-row base (local)
    const int g  = (tid >> 2) & 7;
    const int tq = tid & 3;
    int R[4] = { wb + g, wb + g + 8, wb + g + 16, wb + g + 24 };

    u64 qa[4][4];
#pragma unroll
    for (int r = 0; r < 4; r++) {
        const u64* qp_ = reinterpret_cast<const u64*>(&qS[R[r] * 10]);
#pragma unroll
        for (int k = 0; k < 4; k++) qa[r][k] = qp_[k];
    }

    float cacc[56];
#pragma unroll
    for (int k = 0; k < 56; k++) cacc[k] = 0.f;
    float sS[4] = {0.f, 0.f, 0.f, 0.f};

    const unsigned* Wu = reinterpret_cast<const unsigned*>(Wt);
#pragma unroll 1
    for (int kt = 0; kt < 15; kt++) {
        int jb = kt * 16 + 2 * tq;
        float ev[4][4];
#pragma unroll
        for (int p = 0; p < 4; p++) {
            int j = jb + ((p >> 1) << 3) + (p & 1);
            const ulonglong2* rp = reinterpret_cast<const ulonglong2*>(&rootsS[j * 8]);
            ulonglong2 ra = rp[0], rb = rp[1];
            float kb = kbcS[j];
#pragma unroll
            for (int r = 0; r < 4; r++) {
                u64 d = f2fma(qa[r][1], ra.y, f2mul(qa[r][0], ra.x));
                d = f2fma(qa[r][2], rb.x, d);
                d = f2fma(qa[r][3], rb.y, d);
                float lo, hi; upk(lo, hi, d);
                ev[p][r] = ex2a(fmaf(lo + hi, C, -kb));
            }
        }
#pragma unroll
        for (int r = 0; r < 4; r++) sS[r] += (ev[0][r] + ev[1][r]) + (ev[2][r] + ev[3][r]);
        unsigned aT0[4], aT1[4];
        aT0[0] = pk16(ev[0][0], ev[1][0]); aT0[1] = pk16(ev[0][1], ev[1][1]);
        aT0[2] = pk16(ev[2][0], ev[3][0]); aT0[3] = pk16(ev[2][1], ev[3][1]);
        aT1[0] = pk16(ev[0][2], ev[1][2]); aT1[1] = pk16(ev[0][3], ev[1][3]);
        aT1[2] = pk16(ev[2][2], ev[3][2]); aT1[3] = pk16(ev[2][3], ev[3][3]);

        unsigned kw = (unsigned)(kt * 8 + tq);
#pragma unroll
        for (int n = 0; n < 7; n++) {
            unsigned bidx = (unsigned)(n * 8 + g) * (WT_STRIDE / 2) + kw;
            unsigned bv0 = Wu[bidx], bv1 = Wu[bidx + 4];
            mma16816(&cacc[n * 8],     aT0, bv0, bv1);
            mma16816(&cacc[n * 8 + 4], aT1, bv0, bv1);
        }
    }

    // per-row softmax sums (quad reduction) -> reciprocal
#pragma unroll
    for (int r = 0; r < 4; r++) {
        sS[r] += __shfl_xor_sync(0xFFFFFFFFu, sS[r], 1);
        sS[r] += __shfl_xor_sync(0xFFFFFFFFu, sS[r], 2);
        sS[r] = 1.0f / sS[r];
    }

    // all MMA reads of Wt done -> reuse region as outS
    __syncthreads();
#pragma unroll
    for (int n = 0; n < 7; n++) {
#pragma unroll
        for (int tl = 0; tl < 2; tl++) {
            const float* c = &cacc[n * 8 + tl * 4];
            int ra = tl * 2, rb = tl * 2 + 1;
            float2* pa = reinterpret_cast<float2*>(&outS[R[ra] * 60 + n * 8 + 2 * tq]);
            float2* pb = reinterpret_cast<float2*>(&outS[R[rb] * 60 + n * 8 + 2 * tq]);
            *pa = make_float2(c[0] * sS[ra], c[1] * sS[ra]);
            *pb = make_float2(c[2] * sS[rb], c[3] * sS[rb]);
        }
    }
    __syncthreads();

    // gather own row back as packed u64 accumulators
    u64 acc[28];
    {
        const u64* op = reinterpret_cast<const u64*>(&outS[tid * 60]);
#pragma unroll
        for (int k = 0; k < 28; k++) acc[k] = op[k];
    }

    // ---------------- residual E8 quantization + level gathers (fp32 exact) ----------------
    float invd = expf(-ld[0]);
    {
        float res[8];
        const u64* qp_ = reinterpret_cast<const u64*>(&qS[tid * 10]);
#pragma unroll
        for (int k = 0; k < 4; k++) upk(res[2 * k], res[2 * k + 1], qp_[k]);
        float s = 2.f, gg = 1.f;
#pragma unroll
        for (int lev = 0; lev < 8; lev++) {
            int idx = decode_step(res, s);
            if (lev > 0) {
                u64 gb = pk(gg, gg);
                const ulonglong2* ep = reinterpret_cast<const ulonglong2*>(le + ((size_t)lev * 240 + idx) * 52);
#pragma unroll
                for (int k = 0; k < 13; k++) {
                    ulonglong2 w = __ldg(&ep[k]);
                    acc[2 * k]     = f2fma(gb, w.x, acc[2 * k]);
                    acc[2 * k + 1] = f2fma(gb, w.y, acc[2 * k + 1]);
                }
                ulonglong2 cv = __ldg(reinterpret_cast<const ulonglong2*>(rctl + ((size_t)(lev - 1) * 240 + idx) * 4));
                acc[26] = f2fma(gb, cv.x, acc[26]); acc[27] = f2fma(gb, cv.y, acc[27]);
            }
            s *= invd; gg *= invd;
        }
    }

    // ---------------- gated refine MLP (fp32): rw1 const LDC, rw2 smem LDS ----------------
    {
        float gate = 1.0f / (1.0f + expf(-rgate[0]));
        u64 gateb = pk(gate, gate);
        u64 r2a[26];
#pragma unroll
        for (int k = 0; k < 26; k++) r2a[k] = 0ull;
#pragma unroll 2
        for (int c = 0; c < 52; c++) {
            u64 p = pk(rb1S[c], 0.f);
            const ulonglong2* wr = reinterpret_cast<const ulonglong2*>(&c_tab[c * 52]);
#pragma unroll
            for (int k = 0; k < 13; k++) {
                ulonglong2 w = wr[k];
                p = f2fma(acc[2 * k], w.x, p);
                p = f2fma(acc[2 * k + 1], w.y, p);
            }
            float pl, ph; upk(pl, ph, p);
            float gv = gelu_exact(pl + ph);
            u64 gvb = pk(gv, gv);
            const ulonglong2* w2r = reinterpret_cast<const ulonglong2*>(&rw2TS[c * 52]);
#pragma unroll
            for (int k = 0; k < 13; k++) {
                ulonglong2 w = w2r[k];
                r2a[2 * k]     = f2fma(gvb, w.x, r2a[2 * k]);
                r2a[2 * k + 1] = f2fma(gvb, w.y, r2a[2 * k + 1]);
            }
        }
        const u64* rb2p = reinterpret_cast<const u64*>(rb2S);
#pragma unroll
        for (int k = 0; k < 26; k++)
            acc[k] = f2fma(gateb, f2add(r2a[k], rb2p[k]), acc[k]);
    }

    if (grow < B) {
        float4* op = reinterpret_cast<float4*>(out + (size_t)grow * 56);
#pragma unroll
        for (int c4 = 0; c4 < 14; c4++) {
            float4 v;
            upk(v.x, v.y, acc[2 * c4]); upk(v.z, v.w, acc[2 * c4 + 1]);
            op[c4] = v;
        }
    }
}

extern "C" void kernel_launch(void* const* d_in, const int* in_sizes, int n_in,
                              void* d_out, int out_size) {
    const float* obs   = (const float*)d_in[0];
    const float* w1    = (const float*)d_in[1];
    const float* b1    = (const float*)d_in[2];
    const float* w2    = (const float*)d_in[3];
    const float* b2    = (const float*)d_in[4];
    const float* le    = (const float*)d_in[5];
    const float* bctl  = (const float*)d_in[6];
    const float* rctl  = (const float*)d_in[7];
    const float* bc    = (const float*)d_in[8];
    const float* ld    = (const float*)d_in[9];
    const float* rw1   = (const float*)d_in[10];
    const float* rb1   = (const float*)d_in[11];
    const float* rw2   = (const float*)d_in[12];
    const float* rb2   = (const float*)d_in[13];
    const float* rgate = (const float*)d_in[14];
    float* out = (float*)d_out;

    int B = in_sizes[0] / 14;

    prep_kernel<<<(CTAB_N + 255) / 256, 256>>>(rw1);

    void* c_addr = nullptr;
    void* s_addr = nullptr;
    cudaGetSymbolAddress(&c_addr, c_tab);
    cudaGetSymbolAddress(&s_addr, g_stage);
    cudaMemcpyAsync(c_addr, s_addr, CTAB_N * sizeof(float), cudaMemcpyDeviceToDevice, 0);

    cudaFuncSetAttribute(rcpl_kernel, cudaFuncAttributeMaxDynamicSharedMemorySize, SMEM_REQ);
    int blocks = (B + TPB - 1) / TPB;
    rcpl_kernel<<<blocks, TPB, SMEM_REQ>>>(
        obs, w1, b1, w2, b2, le, bctl, rctl, bc, ld, rb1, rw2, rb2, rgate, out, B);
}

// round 12
// speedup vs baseline: 1.4357x; 1.0666x over previous
#include <cuda_runtime.h>
#include <cuda_fp16.h>
#include <math.h>

#define TPB 128

__device__ __align__(16) float g_roots[240 * 8];

// ---------------- dynamic smem layout (byte offsets, 16B-aligned base) ----------------
#define OFF_WT    0        // fp16 Wt softmax [64][248] = 31744 B; aliased by outS fp32 [128][60]
#define WT_STRIDE 248
#define OFF_W1H   31744    // fp16 refine W1 [64][72] = 9216 B (zero-padded)
#define OFF_W2H   40960    // fp16 refine W2 [64][72] = 9216 B
#define RW_STRIDE 72
#define OFF_ROOTS 50176    // 1920 f
#define OFF_KBC   57856    // 240 f
#define OFF_W1    58816    // 448 f
#define OFF_W2T   60608    // 256 f
#define OFF_B1    61632    // 32 f
#define OFF_B2    61760    // 8 f
#define OFF_RB1   61792    // 56 f (padded)
#define OFF_RB2   62016    // 56 f (padded)
#define OFF_QS    62240    // 128 x 10 f
#define SMEM_REQ  67360

typedef unsigned long long u64;

// ---------------- PTX helpers ----------------
__device__ __forceinline__ u64 pk(float x, float y) {
    u64 r; asm("mov.b64 %0,{%1,%2};" : "=l"(r) : "f"(x), "f"(y)); return r;
}
__device__ __forceinline__ void upk(float& x, float& y, u64 v) {
    asm("mov.b64 {%0,%1},%2;" : "=f"(x), "=f"(y) : "l"(v));
}
__device__ __forceinline__ u64 f2fma(u64 a, u64 b, u64 c) {
    u64 d; asm("fma.rn.f32x2 %0,%1,%2,%3;" : "=l"(d) : "l"(a), "l"(b), "l"(c)); return d;
}
__device__ __forceinline__ u64 f2mul(u64 a, u64 b) {
    u64 d; asm("mul.rn.f32x2 %0,%1,%2;" : "=l"(d) : "l"(a), "l"(b)); return d;
}
__device__ __forceinline__ float ex2a(float x) {
    float y; asm("ex2.approx.ftz.f32 %0,%1;" : "=f"(y) : "f"(x)); return y;
}
// f16x2 with `lo` in the low half
__device__ __forceinline__ unsigned pk16(float lo, float hi) {
    unsigned d; asm("cvt.rn.f16x2.f32 %0,%1,%2;" : "=r"(d) : "f"(hi), "f"(lo)); return d;
}
// hi/lo split for fp32-accurate fp16 MMA (A-side correction)
__device__ __forceinline__ void split16(float x, float y, unsigned& hi, unsigned& lo) {
    hi = pk16(x, y);
    __half2 h = *reinterpret_cast<__half2*>(&hi);
    float2 f = __half22float2(h);
    lo = pk16(x - f.x, y - f.y);
}
// m16n8k16 row.col f16xf16 -> f32
__device__ __forceinline__ void mma16816(float* c, const unsigned a[4], unsigned b0, unsigned b1) {
    asm volatile("mma.sync.aligned.m16n8k16.row.col.f32.f16.f16.f32 "
        "{%0,%1,%2,%3}, {%4,%5,%6,%7}, {%8,%9}, {%0,%1,%2,%3};"
        : "+f"(c[0]), "+f"(c[1]), "+f"(c[2]), "+f"(c[3])
        : "r"(a[0]), "r"(a[1]), "r"(a[2]), "r"(a[3]), "r"(b0), "r"(b1));
}

// ---------------- prep: E8 roots only ----------------
__global__ void prep_kernel() {
    int i = blockIdx.x * blockDim.x + threadIdx.x;
    if (i >= 240) return;
    float v[8];
#pragma unroll
    for (int k = 0; k < 8; k++) v[k] = 0.f;
    if (i < 112) {
        int p = i >> 2, sb = i & 3;
        int a = 0, rem = p;
        while (rem >= 7 - a) { rem -= (7 - a); a++; }
        int b = a + 1 + rem;
        v[a] = (sb & 2) ? -1.f : 1.f;
        v[b] = (sb & 1) ? -1.f : 1.f;
    } else {
        int b = (i - 112) << 1;
        if (__popc(b) & 1) b |= 1;
#pragma unroll
        for (int k = 0; k < 8; k++) v[k] = ((b >> k) & 1) ? -0.5f : 0.5f;
    }
#pragma unroll
    for (int k = 0; k < 8; k++) g_roots[i * 8 + k] = v[k];
}

__device__ __forceinline__ float gelu_exact(float x) {
    return 0.5f * x * (1.0f + erff(x * 0.70710678118654752f));
}

// Analytic nearest-E8-root decode, subtracts root*s in place.
__device__ __forceinline__ int decode_step(float res[8], float s) {
    float a[8];
#pragma unroll
    for (int k = 0; k < 8; k++) a[k] = fabsf(res[k]);
    int m1 = 0; float v1 = a[0];
#pragma unroll
    for (int k = 1; k < 8; k++) if (a[k] > v1) { v1 = a[k]; m1 = k; }
    int m2 = -1; float v2 = -1.f;
#pragma unroll
    for (int k = 0; k < 8; k++) if (k != m1 && a[k] > v2) { v2 = a[k]; m2 = k; }
    float valA = v1 + v2;
    float sum = 0.f;
#pragma unroll
    for (int k = 0; k < 8; k++) sum += a[k];
    int mask = 0;
#pragma unroll
    for (int k = 0; k < 8; k++) mask |= (res[k] < 0.f) ? (1 << k) : 0;
    int km = 0; float vm = a[0];
#pragma unroll
    for (int k = 1; k < 8; k++) if (a[k] < vm) { vm = a[k]; km = k; }
    int par = __popc(mask) & 1;
    float valB = 0.5f * sum - (par ? vm : 0.f);
    int idx;
    if (valA >= valB) {
        int i = (m1 < m2) ? m1 : m2, jj = (m1 < m2) ? m2 : m1;
        int bi = (res[i] < 0.f) ? 1 : 0, bj = (res[jj] < 0.f) ? 1 : 0;
        idx = (7 * i - (i * (i - 1)) / 2 + (jj - i - 1)) * 4 + bi * 2 + bj;
        float di = bi ? -s : s, dj = bj ? -s : s;
#pragma unroll
        for (int k = 0; k < 8; k++) {
            if (k == i)  res[k] -= di;
            if (k == jj) res[k] -= dj;
        }
    } else {
        int bits = par ? (mask ^ (1 << km)) : mask;
        idx = 112 + (bits >> 1);
        float hs = 0.5f * s;
#pragma unroll
        for (int k = 0; k < 8; k++) res[k] -= ((bits >> k) & 1) ? -hs : hs;
    }
    return idx;
}

__global__ __launch_bounds__(TPB, 3) void rcpl_kernel(
    const float* __restrict__ obs,   const float* __restrict__ w1, const float* __restrict__ b1,
    const float* __restrict__ w2,    const float* __restrict__ b2,
    const float* __restrict__ le,    const float* __restrict__ bctl,
    const float* __restrict__ rctl,  const float* __restrict__ bc,
    const float* __restrict__ ld,
    const float* __restrict__ rb1,   const float* __restrict__ rw1,
    const float* __restrict__ rw2,   const float* __restrict__ rb2,
    const float* __restrict__ rgate, float* __restrict__ out, int B)
{
    extern __shared__ __align__(16) char sm[];
    __half*   Wt     = reinterpret_cast<__half*>(sm + OFF_WT);
    float*    outS   = reinterpret_cast<float*>(sm + OFF_WT);   // alias, used after Wt reads finish
    __half*   W1H    = reinterpret_cast<__half*>(sm + OFF_W1H);
    __half*   W2H    = reinterpret_cast<__half*>(sm + OFF_W2H);
    float*    rootsS = reinterpret_cast<float*>(sm + OFF_ROOTS);
    float*    kbcS   = reinterpret_cast<float*>(sm + OFF_KBC);
    float*    w1S    = reinterpret_cast<float*>(sm + OFF_W1);
    float*    w2TS   = reinterpret_cast<float*>(sm + OFF_W2T);
    float*    b1S    = reinterpret_cast<float*>(sm + OFF_B1);
    float*    b2S    = reinterpret_cast<float*>(sm + OFF_B2);
    float*    rb1S   = reinterpret_cast<float*>(sm + OFF_RB1);
    float*    rb2S   = reinterpret_cast<float*>(sm + OFF_RB2);
    float*    qS     = reinterpret_cast<float*>(sm + OFF_QS);

    const float C = 1.0201941611100342f;   // log2(e)/sqrt(2)
    const int tid = threadIdx.x;

    // zero softmax W-table + refine W tables (padding must be 0)
    {
        unsigned* wz = reinterpret_cast<unsigned*>(Wt);
        for (int i = tid; i < (64 * WT_STRIDE) / 2; i += TPB) wz[i] = 0u;
        unsigned* z1 = reinterpret_cast<unsigned*>(W1H);
        unsigned* z2 = reinterpret_cast<unsigned*>(W2H);
        for (int i = tid; i < (64 * RW_STRIDE) / 2; i += TPB) { z1[i] = 0u; z2[i] = 0u; }
    }
    __syncthreads();
    for (int i = tid; i < 240 * 56; i += TPB) {
        int j = i / 56, c = i - j * 56;
        float v = (c < 52) ? le[j * 52 + c] : bctl[j * 4 + (c - 52)];
        Wt[c * WT_STRIDE + j] = __float2half_rn(v);
    }
    for (int i = tid; i < 52 * 52; i += TPB) {
        int n = i / 52, k = i - n * 52;
        W1H[n * RW_STRIDE + k] = __float2half_rn(rw1[i]);
        W2H[n * RW_STRIDE + k] = __float2half_rn(rw2[i]);
    }
    for (int i = tid; i < 1920; i += TPB) rootsS[i] = g_roots[i];
    for (int i = tid; i < 240;  i += TPB) kbcS[i] = bc[i] + 2.0f * C;
    for (int i = tid; i < 448;  i += TPB) w1S[i] = w1[i];
    for (int i = tid; i < 256;  i += TPB) { int l = i >> 3, j = i & 7; w2TS[i] = w2[j * 32 + l]; }
    for (int i = tid; i < 32;   i += TPB) b1S[i] = b1[i];
    for (int i = tid; i < 8;    i += TPB) b2S[i] = b2[i];
    for (int i = tid; i < 56;   i += TPB) {
        rb1S[i] = (i < 52) ? rb1[i] : 0.f;
        rb2S[i] = (i < 52) ? rb2[i] : 0.f;
    }
    __syncthreads();

    int grow = blockIdx.x * TPB + tid;
    int row = (grow < B) ? grow : (B - 1);

    // ---------------- projection 14 -> 32 -> 8 -> qS ----------------
    {
        float x[14];
        const float2* p0 = reinterpret_cast<const float2*>(obs + (size_t)row * 14);
#pragma unroll
        for (int k = 0; k < 7; k++) { float2 v = p0[k]; x[2 * k] = v.x; x[2 * k + 1] = v.y; }
        float q[8];
#pragma unroll
        for (int j = 0; j < 8; j++) q[j] = b2S[j];
#pragma unroll 2
        for (int l = 0; l < 32; l++) {
            float h = b1S[l];
            const float2* wr = reinterpret_cast<const float2*>(&w1S[l * 14]);
#pragma unroll
            for (int k = 0; k < 7; k++) { float2 w = wr[k]; h = fmaf(x[2 * k], w.x, h); h = fmaf(x[2 * k + 1], w.y, h); }
            float g = gelu_exact(h);
            const float4* wt = reinterpret_cast<const float4*>(&w2TS[l * 8]);
            float4 u0 = wt[0], u1 = wt[1];
            q[0] = fmaf(g, u0.x, q[0]); q[1] = fmaf(g, u0.y, q[1]);
            q[2] = fmaf(g, u0.z, q[2]); q[3] = fmaf(g, u0.w, q[3]);
            q[4] = fmaf(g, u1.x, q[4]); q[5] = fmaf(g, u1.y, q[5]);
            q[6] = fmaf(g, u1.z, q[6]); q[7] = fmaf(g, u1.w, q[7]);
        }
        float n2 = 0.f;
#pragma unroll
        for (int j = 0; j < 8; j++) n2 = fmaf(q[j], q[j], n2);
        float sc = 1.4142135623730951f / fmaxf(sqrtf(n2), 1e-12f);
#pragma unroll
        for (int j = 0; j < 8; j++) qS[tid * 10 + j] = q[j] * sc;
    }
    __syncthreads();

    // ---------------- dot/exp -> A fragments + softmax HMMA ----------------
    const int wb = (tid >> 5) << 5;
    const int g  = (tid >> 2) & 7;
    const int tq = tid & 3;
    int R[4] = { wb + g, wb + g + 8, wb + g + 16, wb + g + 24 };

    u64 qa[4][4];
#pragma unroll
    for (int r = 0; r < 4; r++) {
        const u64* qp_ = reinterpret_cast<const u64*>(&qS[R[r] * 10]);
#pragma unroll
        for (int k = 0; k < 4; k++) qa[r][k] = qp_[k];
    }

    float cacc[56];
#pragma unroll
    for (int k = 0; k < 56; k++) cacc[k] = 0.f;
    float sS[4] = {0.f, 0.f, 0.f, 0.f};

    const unsigned* Wu = reinterpret_cast<const unsigned*>(Wt);
#pragma unroll 1
    for (int kt = 0; kt < 15; kt++) {
        int jb = kt * 16 + 2 * tq;
        float ev[4][4];
#pragma unroll
        for (int p = 0; p < 4; p++) {
            int j = jb + ((p >> 1) << 3) + (p & 1);
            const ulonglong2* rp = reinterpret_cast<const ulonglong2*>(&rootsS[j * 8]);
            ulonglong2 ra = rp[0], rb = rp[1];
            float kb = kbcS[j];
#pragma unroll
            for (int r = 0; r < 4; r++) {
                u64 d = f2fma(qa[r][1], ra.y, f2mul(qa[r][0], ra.x));
                d = f2fma(qa[r][2], rb.x, d);
                d = f2fma(qa[r][3], rb.y, d);
                float lo, hi; upk(lo, hi, d);
                ev[p][r] = ex2a(fmaf(lo + hi, C, -kb));
            }
        }
#pragma unroll
        for (int r = 0; r < 4; r++) sS[r] += (ev[0][r] + ev[1][r]) + (ev[2][r] + ev[3][r]);
        unsigned aT0[4], aT1[4];
        aT0[0] = pk16(ev[0][0], ev[1][0]); aT0[1] = pk16(ev[0][1], ev[1][1]);
        aT0[2] = pk16(ev[2][0], ev[3][0]); aT0[3] = pk16(ev[2][1], ev[3][1]);
        aT1[0] = pk16(ev[0][2], ev[1][2]); aT1[1] = pk16(ev[0][3], ev[1][3]);
        aT1[2] = pk16(ev[2][2], ev[3][2]); aT1[3] = pk16(ev[2][3], ev[3][3]);

        unsigned kw = (unsigned)(kt * 8 + tq);
#pragma unroll
        for (int n = 0; n < 7; n++) {
            unsigned bidx = (unsigned)(n * 8 + g) * (WT_STRIDE / 2) + kw;
            unsigned bv0 = Wu[bidx], bv1 = Wu[bidx + 4];
            mma16816(&cacc[n * 8],     aT0, bv0, bv1);
            mma16816(&cacc[n * 8 + 4], aT1, bv0, bv1);
        }
    }

#pragma unroll
    for (int r = 0; r < 4; r++) {
        sS[r] += __shfl_xor_sync(0xFFFFFFFFu, sS[r], 1);
        sS[r] += __shfl_xor_sync(0xFFFFFFFFu, sS[r], 2);
        sS[r] = 1.0f / sS[r];
    }

    // all MMA reads of Wt done -> reuse region as outS
    __syncthreads();
#pragma unroll
    for (int n = 0; n < 7; n++) {
#pragma unroll
        for (int tl = 0; tl < 2; tl++) {
            const float* c = &cacc[n * 8 + tl * 4];
            int ra = tl * 2, rb = tl * 2 + 1;
            float2* pa = reinterpret_cast<float2*>(&outS[R[ra] * 60 + n * 8 + 2 * tq]);
            float2* pb = reinterpret_cast<float2*>(&outS[R[rb] * 60 + n * 8 + 2 * tq]);
            *pa = make_float2(c[0] * sS[ra], c[1] * sS[ra]);
            *pb = make_float2(c[2] * sS[rb], c[3] * sS[rb]);
        }
    }
    __syncthreads();

    // ---------------- residual E8 decode + level gathers (fp32 exact, own row) ----------------
    {
        u64 acc[28];
        const u64* op = reinterpret_cast<const u64*>(&outS[tid * 60]);
#pragma unroll
        for (int k = 0; k < 28; k++) acc[k] = op[k];

        float invd = expf(-ld[0]);
        float res[8];
        const u64* qp_ = reinterpret_cast<const u64*>(&qS[tid * 10]);
#pragma unroll
        for (int k = 0; k < 4; k++) upk(res[2 * k], res[2 * k + 1], qp_[k]);
        float s = 2.f, gg = 1.f;
#pragma unroll
        for (int lev = 0; lev < 8; lev++) {
            int idx = decode_step(res, s);
            if (lev > 0) {
                u64 gb = pk(gg, gg);
                const ulonglong2* ep = reinterpret_cast<const ulonglong2*>(le + ((size_t)lev * 240 + idx) * 52);
#pragma unroll
                for (int k = 0; k < 13; k++) {
                    ulonglong2 w = __ldg(&ep[k]);
                    acc[2 * k]     = f2fma(gb, w.x, acc[2 * k]);
                    acc[2 * k + 1] = f2fma(gb, w.y, acc[2 * k + 1]);
                }
                ulonglong2 cv = __ldg(reinterpret_cast<const ulonglong2*>(rctl + ((size_t)(lev - 1) * 240 + idx) * 4));
                acc[26] = f2fma(gb, cv.x, acc[26]); acc[27] = f2fma(gb, cv.y, acc[27]);
            }
            s *= invd; gg *= invd;
        }
        u64* ow = reinterpret_cast<u64*>(&outS[tid * 60]);
#pragma unroll
        for (int k = 0; k < 28; k++) ow[k] = acc[k];
    }
    __syncwarp();

    // ---------------- gated refine MLP via HMMA (warp-local rows) ----------------
    {
        const unsigned* W1Hu = reinterpret_cast<const unsigned*>(W1H);
        const unsigned* W2Hu = reinterpret_cast<const unsigned*>(W2H);
        float gate = 1.0f / (1.0f + expf(-rgate[0]));

#pragma unroll 1
        for (int rt = 0; rt < 2; rt++) {
            int ra = wb + 16 * rt + g, rbr = ra + 8;

            // layer-1 A fragments (hi/lo split), k masked to <52 (exclude ctrl cols)
            unsigned A1h[16], A1l[16];
#pragma unroll
            for (int kt = 0; kt < 4; kt++) {
                int k0 = kt * 16 + 2 * tq;
#pragma unroll
                for (int e = 0; e < 4; e++) {
                    int rr = (e & 1) ? rbr : ra;
                    int kk = k0 + ((e >> 1) << 3);
                    float2 v = (kk < 52) ? *reinterpret_cast<const float2*>(&outS[rr * 60 + kk])
                                         : make_float2(0.f, 0.f);
                    split16(v.x, v.y, A1h[kt * 4 + e], A1l[kt * 4 + e]);
                }
            }

            float C2[28];
#pragma unroll
            for (int k = 0; k < 28; k++) C2[k] = 0.f;

#pragma unroll 1
            for (int kt2 = 0; kt2 < 4; kt2++) {
                float c1[2][4] = {{0.f,0.f,0.f,0.f},{0.f,0.f,0.f,0.f}};
#pragma unroll
                for (int kt = 0; kt < 4; kt++) {
#pragma unroll
                    for (int h2 = 0; h2 < 2; h2++) {
                        unsigned bi = (unsigned)(((2 * kt2 + h2) * 8 + g) * (RW_STRIDE / 2) + kt * 8 + tq);
                        unsigned b0 = W1Hu[bi], b1v = W1Hu[bi + 4];
                        mma16816(c1[h2], &A1h[kt * 4], b0, b1v);
                        mma16816(c1[h2], &A1l[kt * 4], b0, b1v);
                    }
                }
                unsigned a2h[4], a2l[4];
#pragma unroll
                for (int h2 = 0; h2 < 2; h2++) {
                    int cb = (2 * kt2 + h2) * 8 + 2 * tq;
                    float2 rbp = *reinterpret_cast<const float2*>(&rb1S[cb]);
                    float g0 = gelu_exact(c1[h2][0] + rbp.x);
                    float g1 = gelu_exact(c1[h2][1] + rbp.y);
                    float g2 = gelu_exact(c1[h2][2] + rbp.x);
                    float g3 = gelu_exact(c1[h2][3] + rbp.y);
                    if (h2 == 0) { split16(g0, g1, a2h[0], a2l[0]); split16(g2, g3, a2h[1], a2l[1]); }
                    else         { split16(g0, g1, a2h[2], a2l[2]); split16(g2, g3, a2h[3], a2l[3]); }
                }
#pragma unroll
                for (int nt2 = 0; nt2 < 7; nt2++) {
                    unsigned bi = (unsigned)((nt2 * 8 + g) * (RW_STRIDE / 2) + kt2 * 8 + tq);
                    unsigned b0 = W2Hu[bi], b1v = W2Hu[bi + 4];
                    mma16816(&C2[nt2 * 4], a2h, b0, b1v);
                    mma16816(&C2[nt2 * 4], a2l, b0, b1v);
                }
            }
#pragma unroll
            for (int nt2 = 0; nt2 < 7; nt2++) {
                int c0 = nt2 * 8 + 2 * tq;
                float2 rbp = *reinterpret_cast<const float2*>(&rb2S[c0]);
                float2* pa = reinterpret_cast<float2*>(&outS[ra * 60 + c0]);
                float2 va = *pa;
                va.x = fmaf(gate, C2[nt2 * 4 + 0] + rbp.x, va.x);
                va.y = fmaf(gate, C2[nt2 * 4 + 1] + rbp.y, va.y);
                *pa = va;
                float2* pb = reinterpret_cast<float2*>(&outS[rbr * 60 + c0]);
                float2 vb = *pb;
                vb.x = fmaf(gate, C2[nt2 * 4 + 2] + rbp.x, vb.x);
                vb.y = fmaf(gate, C2[nt2 * 4 + 3] + rbp.y, vb.y);
                *pb = vb;
            }
        }
    }
    __syncwarp();

    // ---------------- final store (own row) ----------------
    if (grow < B) {
        const float4* op = reinterpret_cast<const float4*>(&outS[tid * 60]);
        float4* og = reinterpret_cast<float4*>(out + (size_t)grow * 56);
#pragma unroll
        for (int c4 = 0; c4 < 14; c4++) og[c4] = op[c4];
    }
}

extern "C" void kernel_launch(void* const* d_in, const int* in_sizes, int n_in,
                              void* d_out, int out_size) {
    const float* obs   = (const float*)d_in[0];
    const float* w1    = (const float*)d_in[1];
    const float* b1    = (const float*)d_in[2];
    const float* w2    = (const float*)d_in[3];
    const float* b2    = (const float*)d_in[4];
    const float* le    = (const float*)d_in[5];
    const float* bctl  = (const float*)d_in[6];
    const float* rctl  = (const float*)d_in[7];
    const float* bc    = (const float*)d_in[8];
    const float* ld    = (const float*)d_in[9];
    const float* rw1   = (const float*)d_in[10];
    const float* rb1   = (const float*)d_in[11];
    const float* rw2   = (const float*)d_in[12];
    const float* rb2   = (const float*)d_in[13];
    const float* rgate = (const float*)d_in[14];
    float* out = (float*)d_out;

    int B = in_sizes[0] / 14;

    prep_kernel<<<1, 256>>>();

    cudaFuncSetAttribute(rcpl_kernel, cudaFuncAttributeMaxDynamicSharedMemorySize, SMEM_REQ);
    int blocks = (B + TPB - 1) / TPB;
    rcpl_kernel<<<blocks, TPB, SMEM_REQ>>>(
        obs, w1, b1, w2, b2, le, bctl, rctl, bc, ld, rb1, rw1, rw2, rb2, rgate, out, B);
}

// round 13
// speedup vs baseline: 1.5106x; 1.0522x over previous
#include <cuda_runtime.h>
#include <cuda_fp16.h>
#include <math.h>

#define TPB 128

__device__ __align__(16) float g_roots[240 * 8];

// ---------------- dynamic smem layout (byte offsets, 16B-aligned base) ----------------
#define OFF_WT     0        // fp16 Wt softmax [64][248] = 31744 B; aliased by outS fp32 [128][60]
#define WT_STRIDE  248
#define OFF_W1H    31744    // fp16 refine W1 [64][72] = 9216 B (zero-padded)
#define OFF_W2H    40960    // fp16 refine W2 [64][72] = 9216 B
#define RW_STRIDE  72
#define OFF_ROOTSH 50176    // fp16 roots [240][8] = 3840 B (exact in fp16)
#define OFF_KBC    54016    // 240 f
#define OFF_W1     54976    // 448 f
#define OFF_W2T    56768    // 256 f
#define OFF_B1     57792    // 32 f
#define OFF_B2     57920    // 8 f
#define OFF_RB1    57952    // 56 f (padded)
#define OFF_RB2    58176    // 56 f (padded)
#define OFF_QS     58400    // 128 x 10 f
#define SMEM_REQ   63520

typedef unsigned long long u64;

// ---------------- PTX helpers ----------------
__device__ __forceinline__ u64 pk(float x, float y) {
    u64 r; asm("mov.b64 %0,{%1,%2};" : "=l"(r) : "f"(x), "f"(y)); return r;
}
__device__ __forceinline__ void upk(float& x, float& y, u64 v) {
    asm("mov.b64 {%0,%1},%2;" : "=f"(x), "=f"(y) : "l"(v));
}
__device__ __forceinline__ u64 f2fma(u64 a, u64 b, u64 c) {
    u64 d; asm("fma.rn.f32x2 %0,%1,%2,%3;" : "=l"(d) : "l"(a), "l"(b), "l"(c)); return d;
}
__device__ __forceinline__ float ex2a(float x) {
    float y; asm("ex2.approx.ftz.f32 %0,%1;" : "=f"(y) : "f"(x)); return y;
}
// f16x2 with `lo` in the low half
__device__ __forceinline__ unsigned pk16(float lo, float hi) {
    unsigned d; asm("cvt.rn.f16x2.f32 %0,%1,%2;" : "=r"(d) : "f"(hi), "f"(lo)); return d;
}
// hi/lo split for fp32-accurate fp16 MMA (A-side correction)
__device__ __forceinline__ void split16(float x, float y, unsigned& hi, unsigned& lo) {
    hi = pk16(x, y);
    __half2 h = *reinterpret_cast<__half2*>(&hi);
    float2 f = __half22float2(h);
    lo = pk16(x - f.x, y - f.y);
}
// m16n8k16 row.col f16xf16 -> f32
__device__ __forceinline__ void mma16816(float* c, const unsigned a[4], unsigned b0, unsigned b1) {
    asm volatile("mma.sync.aligned.m16n8k16.row.col.f32.f16.f16.f32 "
        "{%0,%1,%2,%3}, {%4,%5,%6,%7}, {%8,%9}, {%0,%1,%2,%3};"
        : "+f"(c[0]), "+f"(c[1]), "+f"(c[2]), "+f"(c[3])
        : "r"(a[0]), "r"(a[1]), "r"(a[2]), "r"(a[3]), "r"(b0), "r"(b1));
}
// m16n8k8 row.col f16xf16 -> f32
__device__ __forceinline__ void mma1688(float* c, const unsigned a[2], unsigned b) {
    asm volatile("mma.sync.aligned.m16n8k8.row.col.f32.f16.f16.f32 "
        "{%0,%1,%2,%3}, {%4,%5}, {%6}, {%0,%1,%2,%3};"
        : "+f"(c[0]), "+f"(c[1]), "+f"(c[2]), "+f"(c[3])
        : "r"(a[0]), "r"(a[1]), "r"(b));
}

// ---------------- prep: E8 roots only ----------------
__global__ void prep_kernel() {
    int i = blockIdx.x * blockDim.x + threadIdx.x;
    if (i >= 240) return;
    float v[8];
#pragma unroll
    for (int k = 0; k < 8; k++) v[k] = 0.f;
    if (i < 112) {
        int p = i >> 2, sb = i & 3;
        int a = 0, rem = p;
        while (rem >= 7 - a) { rem -= (7 - a); a++; }
        int b = a + 1 + rem;
        v[a] = (sb & 2) ? -1.f : 1.f;
        v[b] = (sb & 1) ? -1.f : 1.f;
    } else {
        int b = (i - 112) << 1;
        if (__popc(b) & 1) b |= 1;
#pragma unroll
        for (int k = 0; k < 8; k++) v[k] = ((b >> k) & 1) ? -0.5f : 0.5f;
    }
#pragma unroll
    for (int k = 0; k < 8; k++) g_roots[i * 8 + k] = v[k];
}

__device__ __forceinline__ float gelu_exact(float x) {
    return 0.5f * x * (1.0f + erff(x * 0.70710678118654752f));
}

// Analytic nearest-E8-root decode, subtracts root*s in place.
__device__ __forceinline__ int decode_step(float res[8], float s) {
    float a[8];
#pragma unroll
    for (int k = 0; k < 8; k++) a[k] = fabsf(res[k]);
    int m1 = 0; float v1 = a[0];
#pragma unroll
    for (int k = 1; k < 8; k++) if (a[k] > v1) { v1 = a[k]; m1 = k; }
    int m2 = -1; float v2 = -1.f;
#pragma unroll
    for (int k = 0; k < 8; k++) if (k != m1 && a[k] > v2) { v2 = a[k]; m2 = k; }
    float valA = v1 + v2;
    float sum = 0.f;
#pragma unroll
    for (int k = 0; k < 8; k++) sum += a[k];
    int mask = 0;
#pragma unroll
    for (int k = 0; k < 8; k++) mask |= (res[k] < 0.f) ? (1 << k) : 0;
    int km = 0; float vm = a[0];
#pragma unroll
    for (int k = 1; k < 8; k++) if (a[k] < vm) { vm = a[k]; km = k; }
    int par = __popc(mask) & 1;
    float valB = 0.5f * sum - (par ? vm : 0.f);
    int idx;
    if (valA >= valB) {
        int i = (m1 < m2) ? m1 : m2, jj = (m1 < m2) ? m2 : m1;
        int bi = (res[i] < 0.f) ? 1 : 0, bj = (res[jj] < 0.f) ? 1 : 0;
        idx = (7 * i - (i * (i - 1)) / 2 + (jj - i - 1)) * 4 + bi * 2 + bj;
        float di = bi ? -s : s, dj = bj ? -s : s;
#pragma unroll
        for (int k = 0; k < 8; k++) {
            if (k == i)  res[k] -= di;
            if (k == jj) res[k] -= dj;
        }
    } else {
        int bits = par ? (mask ^ (1 << km)) : mask;
        idx = 112 + (bits >> 1);
        float hs = 0.5f * s;
#pragma unroll
        for (int k = 0; k < 8; k++) res[k] -= ((bits >> k) & 1) ? -hs : hs;
    }
    return idx;
}

__global__ __launch_bounds__(TPB, 3) void rcpl_kernel(
    const float* __restrict__ obs,   const float* __restrict__ w1, const float* __restrict__ b1,
    const float* __restrict__ w2,    const float* __restrict__ b2,
    const float* __restrict__ le,    const float* __restrict__ bctl,
    const float* __restrict__ rctl,  const float* __restrict__ bc,
    const float* __restrict__ ld,
    const float* __restrict__ rb1,   const float* __restrict__ rw1,
    const float* __restrict__ rw2,   const float* __restrict__ rb2,
    const float* __restrict__ rgate, float* __restrict__ out, int B)
{
    extern __shared__ __align__(16) char sm[];
    __half*   Wt     = reinterpret_cast<__half*>(sm + OFF_WT);
    float*    outS   = reinterpret_cast<float*>(sm + OFF_WT);   // alias, used after Wt reads finish
    __half*   W1H    = reinterpret_cast<__half*>(sm + OFF_W1H);
    __half*   W2H    = reinterpret_cast<__half*>(sm + OFF_W2H);
    __half*   rootsH = reinterpret_cast<__half*>(sm + OFF_ROOTSH);
    float*    kbcS   = reinterpret_cast<float*>(sm + OFF_KBC);
    float*    w1S    = reinterpret_cast<float*>(sm + OFF_W1);
    float*    w2TS   = reinterpret_cast<float*>(sm + OFF_W2T);
    float*    b1S    = reinterpret_cast<float*>(sm + OFF_B1);
    float*    b2S    = reinterpret_cast<float*>(sm + OFF_B2);
    float*    rb1S   = reinterpret_cast<float*>(sm + OFF_RB1);
    float*    rb2S   = reinterpret_cast<float*>(sm + OFF_RB2);
    float*    qS     = reinterpret_cast<float*>(sm + OFF_QS);

    const float C = 1.0201941611100342f;   // log2(e)/sqrt(2)
    const int tid = threadIdx.x;

    // zero softmax W-table + refine W tables (padding must be 0)
    {
        unsigned* wz = reinterpret_cast<unsigned*>(Wt);
        for (int i = tid; i < (64 * WT_STRIDE) / 2; i += TPB) wz[i] = 0u;
        unsigned* z1 = reinterpret_cast<unsigned*>(W1H);
        unsigned* z2 = reinterpret_cast<unsigned*>(W2H);
        for (int i = tid; i < (64 * RW_STRIDE) / 2; i += TPB) { z1[i] = 0u; z2[i] = 0u; }
    }
    __syncthreads();
    for (int i = tid; i < 240 * 56; i += TPB) {
        int j = i / 56, c = i - j * 56;
        float v = (c < 52) ? le[j * 52 + c] : bctl[j * 4 + (c - 52)];
        Wt[c * WT_STRIDE + j] = __float2half_rn(v);
    }
    for (int i = tid; i < 52 * 52; i += TPB) {
        int n = i / 52, k = i - n * 52;
        W1H[n * RW_STRIDE + k] = __float2half_rn(rw1[i]);
        W2H[n * RW_STRIDE + k] = __float2half_rn(rw2[i]);
    }
    for (int i = tid; i < 1920; i += TPB) rootsH[i] = __float2half_rn(g_roots[i]);  // exact
    for (int i = tid; i < 240;  i += TPB) kbcS[i] = bc[i] + 2.0f * C;
    for (int i = tid; i < 448;  i += TPB) w1S[i] = w1[i];
    for (int i = tid; i < 256;  i += TPB) { int l = i >> 3, j = i & 7; w2TS[i] = w2[j * 32 + l]; }
    for (int i = tid; i < 32;   i += TPB) b1S[i] = b1[i];
    for (int i = tid; i < 8;    i += TPB) b2S[i] = b2[i];
    for (int i = tid; i < 56;   i += TPB) {
        rb1S[i] = (i < 52) ? rb1[i] : 0.f;
        rb2S[i] = (i < 52) ? rb2[i] : 0.f;
    }
    __syncthreads();

    int grow = blockIdx.x * TPB + tid;
    int row = (grow < B) ? grow : (B - 1);

    // ---------------- projection 14 -> 32 -> 8 -> qS ----------------
    {
        float x[14];
        const float2* p0 = reinterpret_cast<const float2*>(obs + (size_t)row * 14);
#pragma unroll
        for (int k = 0; k < 7; k++) { float2 v = p0[k]; x[2 * k] = v.x; x[2 * k + 1] = v.y; }
        float q[8];
#pragma unroll
        for (int j = 0; j < 8; j++) q[j] = b2S[j];
#pragma unroll 2
        for (int l = 0; l < 32; l++) {
            float h = b1S[l];
            const float2* wr = reinterpret_cast<const float2*>(&w1S[l * 14]);
#pragma unroll
            for (int k = 0; k < 7; k++) { float2 w = wr[k]; h = fmaf(x[2 * k], w.x, h); h = fmaf(x[2 * k + 1], w.y, h); }
            float g = gelu_exact(h);
            const float4* wt = reinterpret_cast<const float4*>(&w2TS[l * 8]);
            float4 u0 = wt[0], u1 = wt[1];
            q[0] = fmaf(g, u0.x, q[0]); q[1] = fmaf(g, u0.y, q[1]);
            q[2] = fmaf(g, u0.z, q[2]); q[3] = fmaf(g, u0.w, q[3]);
            q[4] = fmaf(g, u1.x, q[4]); q[5] = fmaf(g, u1.y, q[5]);
            q[6] = fmaf(g, u1.z, q[6]); q[7] = fmaf(g, u1.w, q[7]);
        }
        float n2 = 0.f;
#pragma unroll
        for (int j = 0; j < 8; j++) n2 = fmaf(q[j], q[j], n2);
        float sc = 1.4142135623730951f / fmaxf(sqrtf(n2), 1e-12f);
#pragma unroll
        for (int j = 0; j < 8; j++) qS[tid * 10 + j] = q[j] * sc;
    }
    __syncthreads();

    // ---------------- dot GEMM (m16n8k8, roots exact fp16) + exp + softmax HMMA ----------------
    const int wb = (tid >> 5) << 5;
    const int g  = (tid >> 2) & 7;
    const int tq = tid & 3;
    int R[4] = { wb + g, wb + g + 8, wb + g + 16, wb + g + 24 };

    // dot-GEMM A-fragments: (q*C) hi/lo split; dah[m]={row g, row g+8} of m-tile m
    unsigned dah[2][2], dal[2][2];
#pragma unroll
    for (int m = 0; m < 2; m++) {
        float2 v0 = *reinterpret_cast<const float2*>(&qS[(wb + 16 * m + g) * 10 + 2 * tq]);
        float2 v1 = *reinterpret_cast<const float2*>(&qS[(wb + 16 * m + g + 8) * 10 + 2 * tq]);
        split16(v0.x * C, v0.y * C, dah[m][0], dal[m][0]);
        split16(v1.x * C, v1.y * C, dah[m][1], dal[m][1]);
    }

    float cacc[56];
#pragma unroll
    for (int k = 0; k < 56; k++) cacc[k] = 0.f;
    float sS[4] = {0.f, 0.f, 0.f, 0.f};

    const unsigned* Wu = reinterpret_cast<const unsigned*>(Wt);
#pragma unroll 1
    for (int kt = 0; kt < 15; kt++) {
        int nt0 = 2 * kt, nt1 = 2 * kt + 1;
        unsigned rb0 = *reinterpret_cast<const unsigned*>(&rootsH[(nt0 * 8 + g) * 8 + 2 * tq]);
        unsigned rb1v = *reinterpret_cast<const unsigned*>(&rootsH[(nt1 * 8 + g) * 8 + 2 * tq]);
        float c00[4] = {0.f,0.f,0.f,0.f}, c01[4] = {0.f,0.f,0.f,0.f};
        float c10[4] = {0.f,0.f,0.f,0.f}, c11[4] = {0.f,0.f,0.f,0.f};
        mma1688(c00, dah[0], rb0);  mma1688(c00, dal[0], rb0);
        mma1688(c01, dah[0], rb1v); mma1688(c01, dal[0], rb1v);
        mma1688(c10, dah[1], rb0);  mma1688(c10, dal[1], rb0);
        mma1688(c11, dah[1], rb1v); mma1688(c11, dal[1], rb1v);

        float2 kb0 = *reinterpret_cast<const float2*>(&kbcS[nt0 * 8 + 2 * tq]);
        float2 kb1 = *reinterpret_cast<const float2*>(&kbcS[nt1 * 8 + 2 * tq]);

        float e000 = ex2a(c00[0] - kb0.x), e001 = ex2a(c00[1] - kb0.y);
        float e002 = ex2a(c00[2] - kb0.x), e003 = ex2a(c00[3] - kb0.y);
        float e100 = ex2a(c01[0] - kb1.x), e101 = ex2a(c01[1] - kb1.y);
        float e102 = ex2a(c01[2] - kb1.x), e103 = ex2a(c01[3] - kb1.y);
        float e200 = ex2a(c10[0] - kb0.x), e201 = ex2a(c10[1] - kb0.y);
        float e202 = ex2a(c10[2] - kb0.x), e203 = ex2a(c10[3] - kb0.y);
        float e300 = ex2a(c11[0] - kb1.x), e301 = ex2a(c11[1] - kb1.y);
        float e302 = ex2a(c11[2] - kb1.x), e303 = ex2a(c11[3] - kb1.y);

        sS[0] += (e000 + e001) + (e100 + e101);
        sS[1] += (e002 + e003) + (e102 + e103);
        sS[2] += (e200 + e201) + (e300 + e301);
        sS[3] += (e202 + e203) + (e302 + e303);

        unsigned aT0[4], aT1[4];
        aT0[0] = pk16(e000, e001); aT0[1] = pk16(e002, e003);
        aT0[2] = pk16(e100, e101); aT0[3] = pk16(e102, e103);
        aT1[0] = pk16(e200, e201); aT1[1] = pk16(e202, e203);
        aT1[2] = pk16(e300, e301); aT1[3] = pk16(e302, e303);

        unsigned kw = (unsigned)(kt * 8 + tq);
#pragma unroll
        for (int n = 0; n < 7; n++) {
            unsigned bidx = (unsigned)(n * 8 + g) * (WT_STRIDE / 2) + kw;
            unsigned bv0 = Wu[bidx], bv1 = Wu[bidx + 4];
            mma16816(&cacc[n * 8],     aT0, bv0, bv1);
            mma16816(&cacc[n * 8 + 4], aT1, bv0, bv1);
        }
    }

#pragma unroll
    for (int r = 0; r < 4; r++) {
        sS[r] += __shfl_xor_sync(0xFFFFFFFFu, sS[r], 1);
        sS[r] += __shfl_xor_sync(0xFFFFFFFFu, sS[r], 2);
        sS[r] = 1.0f / sS[r];
    }

    // all MMA reads of Wt done -> reuse region as outS
    __syncthreads();
#pragma unroll
    for (int n = 0; n < 7; n++) {
#pragma unroll
        for (int tl = 0; tl < 2; tl++) {
            const float* c = &cacc[n * 8 + tl * 4];
            int ra = tl * 2, rb = tl * 2 + 1;
            float2* pa = reinterpret_cast<float2*>(&outS[R[ra] * 60 + n * 8 + 2 * tq]);
            float2* pb = reinterpret_cast<float2*>(&outS[R[rb] * 60 + n * 8 + 2 * tq]);
            *pa = make_float2(c[0] * sS[ra], c[1] * sS[ra]);
            *pb = make_float2(c[2] * sS[rb], c[3] * sS[rb]);
        }
    }
    __syncthreads();

    // ---------------- residual E8 decode + level gathers (fp32 exact, own row) ----------------
    {
        u64 acc[28];
        const u64* op = reinterpret_cast<const u64*>(&outS[tid * 60]);
#pragma unroll
        for (int k = 0; k < 28; k++) acc[k] = op[k];

        float invd = expf(-ld[0]);
        float res[8];
        const u64* qp_ = reinterpret_cast<const u64*>(&qS[tid * 10]);
#pragma unroll
        for (int k = 0; k < 4; k++) upk(res[2 * k], res[2 * k + 1], qp_[k]);
        float s = 2.f, gg = 1.f;
#pragma unroll
        for (int lev = 0; lev < 8; lev++) {
            int idx = decode_step(res, s);
            if (lev > 0) {
                u64 gb = pk(gg, gg);
                const ulonglong2* ep = reinterpret_cast<const ulonglong2*>(le + ((size_t)lev * 240 + idx) * 52);
#pragma unroll
                for (int k = 0; k < 13; k++) {
                    ulonglong2 w = __ldg(&ep[k]);
                    acc[2 * k]     = f2fma(gb, w.x, acc[2 * k]);
                    acc[2 * k + 1] = f2fma(gb, w.y, acc[2 * k + 1]);
                }
                ulonglong2 cv = __ldg(reinterpret_cast<const ulonglong2*>(rctl + ((size_t)(lev - 1) * 240 + idx) * 4));
                acc[26] = f2fma(gb, cv.x, acc[26]); acc[27] = f2fma(gb, cv.y, acc[27]);
            }
            s *= invd; gg *= invd;
        }
        u64* ow = reinterpret_cast<u64*>(&outS[tid * 60]);
#pragma unroll
        for (int k = 0; k < 28; k++) ow[k] = acc[k];
    }
    __syncwarp();

    // ---------------- gated refine MLP via HMMA (warp-local rows) ----------------
    {
        const unsigned* W1Hu = reinterpret_cast<const unsigned*>(W1H);
        const unsigned* W2Hu = reinterpret_cast<const unsigned*>(W2H);
        float gate = 1.0f / (1.0f + expf(-rgate[0]));

#pragma unroll 1
        for (int rt = 0; rt < 2; rt++) {
            int ra = wb + 16 * rt + g, rbr = ra + 8;

            unsigned A1h[16], A1l[16];
#pragma unroll
            for (int kt = 0; kt < 4; kt++) {
                int k0 = kt * 16 + 2 * tq;
#pragma unroll
                for (int e = 0; e < 4; e++) {
                    int rr = (e & 1) ? rbr : ra;
                    int kk = k0 + ((e >> 1) << 3);
                    float2 v = (kk < 52) ? *reinterpret_cast<const float2*>(&outS[rr * 60 + kk])
                                         : make_float2(0.f, 0.f);
                    split16(v.x, v.y, A1h[kt * 4 + e], A1l[kt * 4 + e]);
                }
            }

            float C2[28];
#pragma unroll
            for (int k = 0; k < 28; k++) C2[k] = 0.f;

#pragma unroll 1
            for (int kt2 = 0; kt2 < 4; kt2++) {
                float c1[2][4] = {{0.f,0.f,0.f,0.f},{0.f,0.f,0.f,0.f}};
#pragma unroll
                for (int kt = 0; kt < 4; kt++) {
#pragma unroll
                    for (int h2 = 0; h2 < 2; h2++) {
                        unsigned bi = (unsigned)(((2 * kt2 + h2) * 8 + g) * (RW_STRIDE / 2) + kt * 8 + tq);
                        unsigned b0 = W1Hu[bi], b1v = W1Hu[bi + 4];
                        mma16816(c1[h2], &A1h[kt * 4], b0, b1v);
                        mma16816(c1[h2], &A1l[kt * 4], b0, b1v);
                    }
                }
                unsigned a2h[4], a2l[4];
#pragma unroll
                for (int h2 = 0; h2 < 2; h2++) {
                    int cb = (2 * kt2 + h2) * 8 + 2 * tq;
                    float2 rbp = *reinterpret_cast<const float2*>(&rb1S[cb]);
                    float g0 = gelu_exact(c1[h2][0] + rbp.x);
                    float g1 = gelu_exact(c1[h2][1] + rbp.y);
                    float g2 = gelu_exact(c1[h2][2] + rbp.x);
                    float g3 = gelu_exact(c1[h2][3] + rbp.y);
                    if (h2 == 0) { split16(g0, g1, a2h[0], a2l[0]); split16(g2, g3, a2h[1], a2l[1]); }
                    else         { split16(g0, g1, a2h[2], a2l[2]); split16(g2, g3, a2h[3], a2l[3]); }
                }
#pragma unroll
                for (int nt2 = 0; nt2 < 7; nt2++) {
                    unsigned bi = (unsigned)((nt2 * 8 + g) * (RW_STRIDE / 2) + kt2 * 8 + tq);
                    unsigned b0 = W2Hu[bi], b1v = W2Hu[bi + 4];
                    mma16816(&C2[nt2 * 4], a2h, b0, b1v);
                    mma16816(&C2[nt2 * 4], a2l, b0, b1v);
                }
            }
#pragma unroll
            for (int nt2 = 0; nt2 < 7; nt2++) {
                int c0 = nt2 * 8 + 2 * tq;
                float2 rbp = *reinterpret_cast<const float2*>(&rb2S[c0]);
                float2* pa = reinterpret_cast<float2*>(&outS[ra * 60 + c0]);
                float2 va = *pa;
                va.x = fmaf(gate, C2[nt2 * 4 + 0] + rbp.x, va.x);
                va.y = fmaf(gate, C2[nt2 * 4 + 1] + rbp.y, va.y);
                *pa = va;
                float2* pb = reinterpret_cast<float2*>(&outS[rbr * 60 + c0]);
                float2 vb = *pb;
                vb.x = fmaf(gate, C2[nt2 * 4 + 2] + rbp.x, vb.x);
                vb.y = fmaf(gate, C2[nt2 * 4 + 3] + rbp.y, vb.y);
                *pb = vb;
            }
        }
    }
    __syncwarp();

    // ---------------- final store (own row) ----------------
    if (grow < B) {
        const float4* op = reinterpret_cast<const float4*>(&outS[tid * 60]);
        float4* og = reinterpret_cast<float4*>(out + (size_t)grow * 56);
#pragma unroll
        for (int c4 = 0; c4 < 14; c4++) og[c4] = op[c4];
    }
}

extern "C" void kernel_launch(void* const* d_in, const int* in_sizes, int n_in,
                              void* d_out, int out_size) {
    const float* obs   = (const float*)d_in[0];
    const float* w1    = (const float*)d_in[1];
    const float* b1    = (const float*)d_in[2];
    const float* w2    = (const float*)d_in[3];
    const float* b2    = (const float*)d_in[4];
    const float* le    = (const float*)d_in[5];
    const float* bctl  = (const float*)d_in[6];
    const float* rctl  = (const float*)d_in[7];
    const float* bc    = (const float*)d_in[8];
    const float* ld    = (const float*)d_in[9];
    const float* rw1   = (const float*)d_in[10];
    const float* rb1   = (const float*)d_in[11];
    const float* rw2   = (const float*)d_in[12];
    const float* rb2   = (const float*)d_in[13];
    const float* rgate = (const float*)d_in[14];
    float* out = (float*)d_out;

    int B = in_sizes[0] / 14;

    prep_kernel<<<1, 256>>>();

    cudaFuncSetAttribute(rcpl_kernel, cudaFuncAttributeMaxDynamicSharedMemorySize, SMEM_REQ);
    int blocks = (B + TPB - 1) / TPB;
    rcpl_kernel<<<blocks, TPB, SMEM_REQ>>>(
        obs, w1, b1, w2, b2, le, bctl, rctl, bc, ld, rb1, rw1, rw2, rb2, rgate, out, B);
}

// round 14
// speedup vs baseline: 1.5712x; 1.0402x over previous
#include <cuda_runtime.h>
#include <cuda_fp16.h>
#include <math.h>

#define TPB 128

__device__ __align__(16) float g_roots[240 * 8];

// ---------------- dynamic smem layout (byte offsets, 16B-aligned base) ----------------
#define OFF_WT     0        // fp16 Wt softmax [64][248] = 31744 B; aliased by outS fp32 [128][60]
#define WT_STRIDE  248
#define OFF_W1H    31744    // fp16 refine W1 [64][72] = 9216 B (zero-padded)
#define OFF_W2H    40960    // fp16 refine W2 [64][72] = 9216 B
#define RW_STRIDE  72
#define OFF_ROOTSH 50176    // fp16 roots [240][8] = 3840 B (exact in fp16)
#define OFF_KBC    54016    // 240 f
#define OFF_W1     54976    // 448 f
#define OFF_W2T    56768    // 256 f
#define OFF_B1     57792    // 32 f
#define OFF_B2     57920    // 8 f
#define OFF_RB1    57952    // 56 f (padded)
#define OFF_RB2    58176    // 56 f (padded)
#define OFF_QS     58400    // 128 x 10 f
#define SMEM_REQ   63520

typedef unsigned long long u64;

// ---------------- PTX helpers ----------------
__device__ __forceinline__ u64 pk(float x, float y) {
    u64 r; asm("mov.b64 %0,{%1,%2};" : "=l"(r) : "f"(x), "f"(y)); return r;
}
__device__ __forceinline__ void upk(float& x, float& y, u64 v) {
    asm("mov.b64 {%0,%1},%2;" : "=f"(x), "=f"(y) : "l"(v));
}
__device__ __forceinline__ u64 f2fma(u64 a, u64 b, u64 c) {
    u64 d; asm("fma.rn.f32x2 %0,%1,%2,%3;" : "=l"(d) : "l"(a), "l"(b), "l"(c)); return d;
}
__device__ __forceinline__ float ex2a(float x) {
    float y; asm("ex2.approx.ftz.f32 %0,%1;" : "=f"(y) : "f"(x)); return y;
}
// f16x2 with `lo` in the low half
__device__ __forceinline__ unsigned pk16(float lo, float hi) {
    unsigned d; asm("cvt.rn.f16x2.f32 %0,%1,%2;" : "=r"(d) : "f"(hi), "f"(lo)); return d;
}
// hi/lo split for fp32-accurate fp16 MMA (A-side correction)
__device__ __forceinline__ void split16(float x, float y, unsigned& hi, unsigned& lo) {
    hi = pk16(x, y);
    __half2 h = *reinterpret_cast<__half2*>(&hi);
    float2 f = __half22float2(h);
    lo = pk16(x - f.x, y - f.y);
}
// m16n8k16 row.col f16xf16 -> f32
__device__ __forceinline__ void mma16816(float* c, const unsigned a[4], unsigned b0, unsigned b1) {
    asm volatile("mma.sync.aligned.m16n8k16.row.col.f32.f16.f16.f32 "
        "{%0,%1,%2,%3}, {%4,%5,%6,%7}, {%8,%9}, {%0,%1,%2,%3};"
        : "+f"(c[0]), "+f"(c[1]), "+f"(c[2]), "+f"(c[3])
        : "r"(a[0]), "r"(a[1]), "r"(a[2]), "r"(a[3]), "r"(b0), "r"(b1));
}
// m16n8k8 row.col f16xf16 -> f32
__device__ __forceinline__ void mma1688(float* c, const unsigned a[2], unsigned b) {
    asm volatile("mma.sync.aligned.m16n8k8.row.col.f32.f16.f16.f32 "
        "{%0,%1,%2,%3}, {%4,%5}, {%6}, {%0,%1,%2,%3};"
        : "+f"(c[0]), "+f"(c[1]), "+f"(c[2]), "+f"(c[3])
        : "r"(a[0]), "r"(a[1]), "r"(b));
}
// 4x 8x8 fp16 tiles in one shot; lane provides its assigned row address
__device__ __forceinline__ void ldsm_x4(unsigned r[4], unsigned addr) {
    asm volatile("ldmatrix.sync.aligned.m8n8.x4.shared.b16 {%0,%1,%2,%3}, [%4];"
        : "=r"(r[0]), "=r"(r[1]), "=r"(r[2]), "=r"(r[3]) : "r"(addr));
}
__device__ __forceinline__ unsigned smem_u32(const void* p) {
    unsigned a; asm("{ .reg .u64 t; cvta.to.shared.u64 t,%1; cvt.u32.u64 %0,t; }" : "=r"(a) : "l"(p));
    return a;
}

// ---------------- prep: E8 roots only ----------------
__global__ void prep_kernel() {
    int i = blockIdx.x * blockDim.x + threadIdx.x;
    if (i >= 240) return;
    float v[8];
#pragma unroll
    for (int k = 0; k < 8; k++) v[k] = 0.f;
    if (i < 112) {
        int p = i >> 2, sb = i & 3;
        int a = 0, rem = p;
        while (rem >= 7 - a) { rem -= (7 - a); a++; }
        int b = a + 1 + rem;
        v[a] = (sb & 2) ? -1.f : 1.f;
        v[b] = (sb & 1) ? -1.f : 1.f;
    } else {
        int b = (i - 112) << 1;
        if (__popc(b) & 1) b |= 1;
#pragma unroll
        for (int k = 0; k < 8; k++) v[k] = ((b >> k) & 1) ? -0.5f : 0.5f;
    }
#pragma unroll
    for (int k = 0; k < 8; k++) g_roots[i * 8 + k] = v[k];
}

__device__ __forceinline__ float gelu_exact(float x) {
    return 0.5f * x * (1.0f + erff(x * 0.70710678118654752f));
}

// Analytic nearest-E8-root decode, subtracts root*s in place.
__device__ __forceinline__ int decode_step(float res[8], float s) {
    float a[8];
#pragma unroll
    for (int k = 0; k < 8; k++) a[k] = fabsf(res[k]);
    int m1 = 0; float v1 = a[0];
#pragma unroll
    for (int k = 1; k < 8; k++) if (a[k] > v1) { v1 = a[k]; m1 = k; }
    int m2 = -1; float v2 = -1.f;
#pragma unroll
    for (int k = 0; k < 8; k++) if (k != m1 && a[k] > v2) { v2 = a[k]; m2 = k; }
    float valA = v1 + v2;
    float sum = 0.f;
#pragma unroll
    for (int k = 0; k < 8; k++) sum += a[k];
    int mask = 0;
#pragma unroll
    for (int k = 0; k < 8; k++) mask |= (res[k] < 0.f) ? (1 << k) : 0;
    int km = 0; float vm = a[0];
#pragma unroll
    for (int k = 1; k < 8; k++) if (a[k] < vm) { vm = a[k]; km = k; }
    int par = __popc(mask) & 1;
    float valB = 0.5f * sum - (par ? vm : 0.f);
    int idx;
    if (valA >= valB) {
        int i = (m1 < m2) ? m1 : m2, jj = (m1 < m2) ? m2 : m1;
        int bi = (res[i] < 0.f) ? 1 : 0, bj = (res[jj] < 0.f) ? 1 : 0;
        idx = (7 * i - (i * (i - 1)) / 2 + (jj - i - 1)) * 4 + bi * 2 + bj;
        float di = bi ? -s : s, dj = bj ? -s : s;
#pragma unroll
        for (int k = 0; k < 8; k++) {
            if (k == i)  res[k] -= di;
            if (k == jj) res[k] -= dj;
        }
    } else {
        int bits = par ? (mask ^ (1 << km)) : mask;
        idx = 112 + (bits >> 1);
        float hs = 0.5f * s;
#pragma unroll
        for (int k = 0; k < 8; k++) res[k] -= ((bits >> k) & 1) ? -hs : hs;
    }
    return idx;
}

__global__ __launch_bounds__(TPB, 3) void rcpl_kernel(
    const float* __restrict__ obs,   const float* __restrict__ w1, const float* __restrict__ b1,
    const float* __restrict__ w2,    const float* __restrict__ b2,
    const float* __restrict__ le,    const float* __restrict__ bctl,
    const float* __restrict__ rctl,  const float* __restrict__ bc,
    const float* __restrict__ ld,
    const float* __restrict__ rb1,   const float* __restrict__ rw1,
    const float* __restrict__ rw2,   const float* __restrict__ rb2,
    const float* __restrict__ rgate, float* __restrict__ out, int B)
{
    extern __shared__ __align__(16) char sm[];
    __half*   Wt     = reinterpret_cast<__half*>(sm + OFF_WT);
    float*    outS   = reinterpret_cast<float*>(sm + OFF_WT);   // alias, used after Wt reads finish
    __half*   W1H    = reinterpret_cast<__half*>(sm + OFF_W1H);
    __half*   W2H    = reinterpret_cast<__half*>(sm + OFF_W2H);
    __half*   rootsH = reinterpret_cast<__half*>(sm + OFF_ROOTSH);
    float*    kbcS   = reinterpret_cast<float*>(sm + OFF_KBC);
    float*    w1S    = reinterpret_cast<float*>(sm + OFF_W1);
    float*    w2TS   = reinterpret_cast<float*>(sm + OFF_W2T);
    float*    b1S    = reinterpret_cast<float*>(sm + OFF_B1);
    float*    b2S    = reinterpret_cast<float*>(sm + OFF_B2);
    float*    rb1S   = reinterpret_cast<float*>(sm + OFF_RB1);
    float*    rb2S   = reinterpret_cast<float*>(sm + OFF_RB2);
    float*    qS     = reinterpret_cast<float*>(sm + OFF_QS);

    const float C = 1.0201941611100342f;   // log2(e)/sqrt(2)
    const int tid = threadIdx.x;

    // zero softmax W-table + refine W tables (padding must be 0)
    {
        unsigned* wz = reinterpret_cast<unsigned*>(Wt);
        for (int i = tid; i < (64 * WT_STRIDE) / 2; i += TPB) wz[i] = 0u;
        unsigned* z1 = reinterpret_cast<unsigned*>(W1H);
        unsigned* z2 = reinterpret_cast<unsigned*>(W2H);
        for (int i = tid; i < (64 * RW_STRIDE) / 2; i += TPB) { z1[i] = 0u; z2[i] = 0u; }
    }
    __syncthreads();
    for (int i = tid; i < 240 * 56; i += TPB) {
        int j = i / 56, c = i - j * 56;
        float v = (c < 52) ? le[j * 52 + c] : bctl[j * 4 + (c - 52)];
        Wt[c * WT_STRIDE + j] = __float2half_rn(v);
    }
    for (int i = tid; i < 52 * 52; i += TPB) {
        int n = i / 52, k = i - n * 52;
        W1H[n * RW_STRIDE + k] = __float2half_rn(rw1[i]);
        W2H[n * RW_STRIDE + k] = __float2half_rn(rw2[i]);
    }
    for (int i = tid; i < 1920; i += TPB) rootsH[i] = __float2half_rn(g_roots[i]);  // exact
    for (int i = tid; i < 240;  i += TPB) kbcS[i] = bc[i] + 2.0f * C;
    for (int i = tid; i < 448;  i += TPB) w1S[i] = w1[i];
    for (int i = tid; i < 256;  i += TPB) { int l = i >> 3, j = i & 7; w2TS[i] = w2[j * 32 + l]; }
    for (int i = tid; i < 32;   i += TPB) b1S[i] = b1[i];
    for (int i = tid; i < 8;    i += TPB) b2S[i] = b2[i];
    for (int i = tid; i < 56;   i += TPB) {
        rb1S[i] = (i < 52) ? rb1[i] : 0.f;
        rb2S[i] = (i < 52) ? rb2[i] : 0.f;
    }
    __syncthreads();

    int grow = blockIdx.x * TPB + tid;
    int row = (grow < B) ? grow : (B - 1);

    // ---------------- projection 14 -> 32 -> 8 -> qS ----------------
    {
        float x[14];
        const float2* p0 = reinterpret_cast<const float2*>(obs + (size_t)row * 14);
#pragma unroll
        for (int k = 0; k < 7; k++) { float2 v = p0[k]; x[2 * k] = v.x; x[2 * k + 1] = v.y; }
        float q[8];
#pragma unroll
        for (int j = 0; j < 8; j++) q[j] = b2S[j];
#pragma unroll 2
        for (int l = 0; l < 32; l++) {
            float h = b1S[l];
            const float2* wr = reinterpret_cast<const float2*>(&w1S[l * 14]);
#pragma unroll
            for (int k = 0; k < 7; k++) { float2 w = wr[k]; h = fmaf(x[2 * k], w.x, h); h = fmaf(x[2 * k + 1], w.y, h); }
            float g = gelu_exact(h);
            const float4* wt = reinterpret_cast<const float4*>(&w2TS[l * 8]);
            float4 u0 = wt[0], u1 = wt[1];
            q[0] = fmaf(g, u0.x, q[0]); q[1] = fmaf(g, u0.y, q[1]);
            q[2] = fmaf(g, u0.z, q[2]); q[3] = fmaf(g, u0.w, q[3]);
            q[4] = fmaf(g, u1.x, q[4]); q[5] = fmaf(g, u1.y, q[5]);
            q[6] = fmaf(g, u1.z, q[6]); q[7] = fmaf(g, u1.w, q[7]);
        }
        float n2 = 0.f;
#pragma unroll
        for (int j = 0; j < 8; j++) n2 = fmaf(q[j], q[j], n2);
        float sc = 1.4142135623730951f / fmaxf(sqrtf(n2), 1e-12f);
#pragma unroll
        for (int j = 0; j < 8; j++) qS[tid * 10 + j] = q[j] * sc;
    }
    __syncthreads();

    // ---------------- dot GEMM (m16n8k8) + exp + softmax HMMA, ldmatrix W-frags ----------------
    const int wb = (tid >> 5) << 5;
    const int g  = (tid >> 2) & 7;
    const int tq = tid & 3;
    int R[4] = { wb + g, wb + g + 8, wb + g + 16, wb + g + 24 };

    // ldmatrix lane-constant base addresses: call i covers tiles 4i..4i+3; tile t=(n= t>>1, khalf= t&1)
    unsigned ldsm_base[4];
    {
        unsigned lane = (unsigned)(tid & 31);
        unsigned WtU = smem_u32(Wt);
#pragma unroll
        for (int i = 0; i < 4; i++) {
            unsigned t = 4u * i + (lane >> 3);
            unsigned n = t >> 1, h = t & 1, r = lane & 7;
            ldsm_base[i] = WtU + ((n * 8u + r) * WT_STRIDE + h * 8u) * 2u;
        }
    }

    // dot-GEMM A-fragments: (q*C) hi/lo split
    unsigned dah[2][2], dal[2][2];
#pragma unroll
    for (int m = 0; m < 2; m++) {
        float2 v0 = *reinterpret_cast<const float2*>(&qS[(wb + 16 * m + g) * 10 + 2 * tq]);
        float2 v1 = *reinterpret_cast<const float2*>(&qS[(wb + 16 * m + g + 8) * 10 + 2 * tq]);
        split16(v0.x * C, v0.y * C, dah[m][0], dal[m][0]);
        split16(v1.x * C, v1.y * C, dah[m][1], dal[m][1]);
    }

    float cacc[56];
#pragma unroll
    for (int k = 0; k < 56; k++) cacc[k] = 0.f;
    float sS[4] = {0.f, 0.f, 0.f, 0.f};

#pragma unroll 1
    for (int kt = 0; kt < 15; kt++) {
        // W-fragments first (independent of this iteration's dots -> latency hidden)
        unsigned bW[16];
        unsigned koff = (unsigned)(kt * 32);
        ldsm_x4(&bW[0],  ldsm_base[0] + koff);
        ldsm_x4(&bW[4],  ldsm_base[1] + koff);
        ldsm_x4(&bW[8],  ldsm_base[2] + koff);
        ldsm_x4(&bW[12], ldsm_base[3] + koff);

        int nt0 = 2 * kt, nt1 = 2 * kt + 1;
        unsigned rb0 = *reinterpret_cast<const unsigned*>(&rootsH[(nt0 * 8 + g) * 8 + 2 * tq]);
        unsigned rb1v = *reinterpret_cast<const unsigned*>(&rootsH[(nt1 * 8 + g) * 8 + 2 * tq]);
        float c00[4] = {0.f,0.f,0.f,0.f}, c01[4] = {0.f,0.f,0.f,0.f};
        float c10[4] = {0.f,0.f,0.f,0.f}, c11[4] = {0.f,0.f,0.f,0.f};
        mma1688(c00, dah[0], rb0);  mma1688(c00, dal[0], rb0);
        mma1688(c01, dah[0], rb1v); mma1688(c01, dal[0], rb1v);
        mma1688(c10, dah[1], rb0);  mma1688(c10, dal[1], rb0);
        mma1688(c11, dah[1], rb1v); mma1688(c11, dal[1], rb1v);

        float2 kb0 = *reinterpret_cast<const float2*>(&kbcS[nt0 * 8 + 2 * tq]);
        float2 kb1 = *reinterpret_cast<const float2*>(&kbcS[nt1 * 8 + 2 * tq]);

        float e000 = ex2a(c00[0] - kb0.x), e001 = ex2a(c00[1] - kb0.y);
        float e002 = ex2a(c00[2] - kb0.x), e003 = ex2a(c00[3] - kb0.y);
        float e100 = ex2a(c01[0] - kb1.x), e101 = ex2a(c01[1] - kb1.y);
        float e102 = ex2a(c01[2] - kb1.x), e103 = ex2a(c01[3] - kb1.y);
        float e200 = ex2a(c10[0] - kb0.x), e201 = ex2a(c10[1] - kb0.y);
        float e202 = ex2a(c10[2] - kb0.x), e203 = ex2a(c10[3] - kb0.y);
        float e300 = ex2a(c11[0] - kb1.x), e301 = ex2a(c11[1] - kb1.y);
        float e302 = ex2a(c11[2] - kb1.x), e303 = ex2a(c11[3] - kb1.y);

        sS[0] += (e000 + e001) + (e100 + e101);
        sS[1] += (e002 + e003) + (e102 + e103);
        sS[2] += (e200 + e201) + (e300 + e301);
        sS[3] += (e202 + e203) + (e302 + e303);

        unsigned aT0[4], aT1[4];
        aT0[0] = pk16(e000, e001); aT0[1] = pk16(e002, e003);
        aT0[2] = pk16(e100, e101); aT0[3] = pk16(e102, e103);
        aT1[0] = pk16(e200, e201); aT1[1] = pk16(e202, e203);
        aT1[2] = pk16(e300, e301); aT1[3] = pk16(e302, e303);

#pragma unroll
        for (int n = 0; n < 7; n++) {
            mma16816(&cacc[n * 8],     aT0, bW[2 * n], bW[2 * n + 1]);
            mma16816(&cacc[n * 8 + 4], aT1, bW[2 * n], bW[2 * n + 1]);
        }
    }

#pragma unroll
    for (int r = 0; r < 4; r++) {
        sS[r] += __shfl_xor_sync(0xFFFFFFFFu, sS[r], 1);
        sS[r] += __shfl_xor_sync(0xFFFFFFFFu, sS[r], 2);
        sS[r] = 1.0f / sS[r];
    }

    // all MMA reads of Wt done -> reuse region as outS
    __syncthreads();
#pragma unroll
    for (int n = 0; n < 7; n++) {
#pragma unroll
        for (int tl = 0; tl < 2; tl++) {
            const float* c = &cacc[n * 8 + tl * 4];
            int ra = tl * 2, rb = tl * 2 + 1;
            float2* pa = reinterpret_cast<float2*>(&outS[R[ra] * 60 + n * 8 + 2 * tq]);
            float2* pb = reinterpret_cast<float2*>(&outS[R[rb] * 60 + n * 8 + 2 * tq]);
            *pa = make_float2(c[0] * sS[ra], c[1] * sS[ra]);
            *pb = make_float2(c[2] * sS[rb], c[3] * sS[rb]);
        }
    }
    __syncthreads();

    // ---------------- residual E8 decode + level gathers (fp32 exact, own row) ----------------
    {
        u64 acc[28];
        const u64* op = reinterpret_cast<const u64*>(&outS[tid * 60]);
#pragma unroll
        for (int k = 0; k < 28; k++) acc[k] = op[k];

        float invd = expf(-ld[0]);
        float res[8];
        const u64* qp_ = reinterpret_cast<const u64*>(&qS[tid * 10]);
#pragma unroll
        for (int k = 0; k < 4; k++) upk(res[2 * k], res[2 * k + 1], qp_[k]);
        float s = 2.f, gg = 1.f;
#pragma unroll
        for (int lev = 0; lev < 8; lev++) {
            int idx = decode_step(res, s);
            if (lev > 0) {
                u64 gb = pk(gg, gg);
                const ulonglong2* ep = reinterpret_cast<const ulonglong2*>(le + ((size_t)lev * 240 + idx) * 52);
#pragma unroll
                for (int k = 0; k < 13; k++) {
                    ulonglong2 w = __ldg(&ep[k]);
                    acc[2 * k]     = f2fma(gb, w.x, acc[2 * k]);
                    acc[2 * k + 1] = f2fma(gb, w.y, acc[2 * k + 1]);
                }
                ulonglong2 cv = __ldg(reinterpret_cast<const ulonglong2*>(rctl + ((size_t)(lev - 1) * 240 + idx) * 4));
                acc[26] = f2fma(gb, cv.x, acc[26]); acc[27] = f2fma(gb, cv.y, acc[27]);
            }
            s *= invd; gg *= invd;
        }
        u64* ow = reinterpret_cast<u64*>(&outS[tid * 60]);
#pragma unroll
        for (int k = 0; k < 28; k++) ow[k] = acc[k];
    }
    __syncwarp();

    // ---------------- gated refine MLP via HMMA (warp-local rows) ----------------
    {
        const unsigned* W1Hu = reinterpret_cast<const unsigned*>(W1H);
        const unsigned* W2Hu = reinterpret_cast<const unsigned*>(W2H);
        float gate = 1.0f / (1.0f + expf(-rgate[0]));

#pragma unroll 1
        for (int rt = 0; rt < 2; rt++) {
            int ra = wb + 16 * rt + g, rbr = ra + 8;

            unsigned A1h[16], A1l[16];
#pragma unroll
            for (int kt = 0; kt < 4; kt++) {
                int k0 = kt * 16 + 2 * tq;
#pragma unroll
                for (int e = 0; e < 4; e++) {
                    int rr = (e & 1) ? rbr : ra;
                    int kk = k0 + ((e >> 1) << 3);
                    float2 v = (kk < 52) ? *reinterpret_cast<const float2*>(&outS[rr * 60 + kk])
                                         : make_float2(0.f, 0.f);
                    split16(v.x, v.y, A1h[kt * 4 + e], A1l[kt * 4 + e]);
                }
            }

            float C2[28];
#pragma unroll
            for (int k = 0; k < 28; k++) C2[k] = 0.f;

#pragma unroll 1
            for (int kt2 = 0; kt2 < 4; kt2++) {
                float c1[2][4] = {{0.f,0.f,0.f,0.f},{0.f,0.f,0.f,0.f}};
#pragma unroll
                for (int kt = 0; kt < 4; kt++) {
#pragma unroll
                    for (int h2 = 0; h2 < 2; h2++) {
                        unsigned bi = (unsigned)(((2 * kt2 + h2) * 8 + g) * (RW_STRIDE / 2) + kt * 8 + tq);
                        unsigned b0 = W1Hu[bi], b1v = W1Hu[bi + 4];
                        mma16816(c1[h2], &A1h[kt * 4], b0, b1v);
                        mma16816(c1[h2], &A1l[kt * 4], b0, b1v);
                    }
                }
                unsigned a2h[4], a2l[4];
#pragma unroll
                for (int h2 = 0; h2 < 2; h2++) {
                    int cb = (2 * kt2 + h2) * 8 + 2 * tq;
                    float2 rbp = *reinterpret_cast<const float2*>(&rb1S[cb]);
                    float g0 = gelu_exact(c1[h2][0] + rbp.x);
                    float g1 = gelu_exact(c1[h2][1] + rbp.y);
                    float g2 = gelu_exact(c1[h2][2] + rbp.x);
                    float g3 = gelu_exact(c1[h2][3] + rbp.y);
                    if (h2 == 0) { split16(g0, g1, a2h[0], a2l[0]); split16(g2, g3, a2h[1], a2l[1]); }
                    else         { split16(g0, g1, a2h[2], a2l[2]); split16(g2, g3, a2h[3], a2l[3]); }
                }
#pragma unroll
                for (int nt2 = 0; nt2 < 7; nt2++) {
                    unsigned bi = (unsigned)((nt2 * 8 + g) * (RW_STRIDE / 2) + kt2 * 8 + tq);
                    unsigned b0 = W2Hu[bi], b1v = W2Hu[bi + 4];
                    mma16816(&C2[nt2 * 4], a2h, b0, b1v);
                    mma16816(&C2[nt2 * 4], a2l, b0, b1v);
                }
            }
#pragma unroll
            for (int nt2 = 0; nt2 < 7; nt2++) {
                int c0 = nt2 * 8 + 2 * tq;
                float2 rbp = *reinterpret_cast<const float2*>(&rb2S[c0]);
                float2* pa = reinterpret_cast<float2*>(&outS[ra * 60 + c0]);
                float2 va = *pa;
                va.x = fmaf(gate, C2[nt2 * 4 + 0] + rbp.x, va.x);
                va.y = fmaf(gate, C2[nt2 * 4 + 1] + rbp.y, va.y);
                *pa = va;
                float2* pb = reinterpret_cast<float2*>(&outS[rbr * 60 + c0]);
                float2 vb = *pb;
                vb.x = fmaf(gate, C2[nt2 * 4 + 2] + rbp.x, vb.x);
                vb.y = fmaf(gate, C2[nt2 * 4 + 3] + rbp.y, vb.y);
                *pb = vb;
            }
        }
    }
    __syncwarp();

    // ---------------- final store (own row) ----------------
    if (grow < B) {
        const float4* op = reinterpret_cast<const float4*>(&outS[tid * 60]);
        float4* og = reinterpret_cast<float4*>(out + (size_t)grow * 56);
#pragma unroll
        for (int c4 = 0; c4 < 14; c4++) og[c4] = op[c4];
    }
}

extern "C" void kernel_launch(void* const* d_in, const int* in_sizes, int n_in,
                              void* d_out, int out_size) {
    const float* obs   = (const float*)d_in[0];
    const float* w1    = (const float*)d_in[1];
    const float* b1    = (const float*)d_in[2];
    const float* w2    = (const float*)d_in[3];
    const float* b2    = (const float*)d_in[4];
    const float* le    = (const float*)d_in[5];
    const float* bctl  = (const float*)d_in[6];
    const float* rctl  = (const float*)d_in[7];
    const float* bc    = (const float*)d_in[8];
    const float* ld    = (const float*)d_in[9];
    const float* rw1   = (const float*)d_in[10];
    const float* rb1   = (const float*)d_in[11];
    const float* rw2   = (const float*)d_in[12];
    const float* rb2   = (const float*)d_in[13];
    const float* rgate = (const float*)d_in[14];
    float* out = (float*)d_out;

    int B = in_sizes[0] / 14;

    prep_kernel<<<1, 256>>>();

    cudaFuncSetAttribute(rcpl_kernel, cudaFuncAttributeMaxDynamicSharedMemorySize, SMEM_REQ);
    int blocks = (B + TPB - 1) / TPB;
    rcpl_kernel<<<blocks, TPB, SMEM_REQ>>>(
        obs, w1, b1, w2, b2, le, bctl, rctl, bc, ld, rb1, rw1, rw2, rb2, rgate, out, B);
}

// round 16
// speedup vs baseline: 1.5719x; 1.0004x over previous
#include <cuda_runtime.h>
#include <cuda_fp16.h>
#include <math.h>

#define TPB 128

__device__ __align__(16) float g_roots[240 * 8];

// ---------------- dynamic smem layout (byte offsets, 16B-aligned base) ----------------
#define OFF_WT     0        // fp16 Wt softmax [64][248] = 31744 B; aliased by outS fp32 [128][60]
#define WT_STRIDE  248
#define OFF_W1H    31744    // fp16 refine W1 [64][72] = 9216 B (zero-padded)
#define OFF_W2H    40960    // fp16 refine W2 [64][72] = 9216 B
#define RW_STRIDE  72
#define OFF_ROOTSH 50176    // fp16 roots [240][8] = 3840 B (exact in fp16)
#define OFF_KBC    54016    // 240 f
#define OFF_W1     54976    // 448 f
#define OFF_W2T    56768    // 256 f
#define OFF_B1     57792    // 32 f
#define OFF_B2     57920    // 8 f
#define OFF_RB1    57952    // 56 f (padded)
#define OFF_RB2    58176    // 56 f (padded)
#define OFF_QS     58400    // 128 x 10 f
#define SMEM_REQ   63520

typedef unsigned long long u64;

// ---------------- PTX helpers ----------------
__device__ __forceinline__ u64 pk(float x, float y) {
    u64 r; asm("mov.b64 %0,{%1,%2};" : "=l"(r) : "f"(x), "f"(y)); return r;
}
__device__ __forceinline__ void upk(float& x, float& y, u64 v) {
    asm("mov.b64 {%0,%1},%2;" : "=f"(x), "=f"(y) : "l"(v));
}
__device__ __forceinline__ u64 f2fma(u64 a, u64 b, u64 c) {
    u64 d; asm("fma.rn.f32x2 %0,%1,%2,%3;" : "=l"(d) : "l"(a), "l"(b), "l"(c)); return d;
}
__device__ __forceinline__ float ex2a(float x) {
    float y; asm("ex2.approx.ftz.f32 %0,%1;" : "=f"(y) : "f"(x)); return y;
}
// f16x2 with `lo` in the low half
__device__ __forceinline__ unsigned pk16(float lo, float hi) {
    unsigned d; asm("cvt.rn.f16x2.f32 %0,%1,%2;" : "=r"(d) : "f"(hi), "f"(lo)); return d;
}
// hi/lo split for fp32-accurate fp16 MMA (A-side correction)
__device__ __forceinline__ void split16(float x, float y, unsigned& hi, unsigned& lo) {
    hi = pk16(x, y);
    __half2 h = *reinterpret_cast<__half2*>(&hi);
    float2 f = __half22float2(h);
    lo = pk16(x - f.x, y - f.y);
}
// m16n8k16 row.col f16xf16 -> f32
__device__ __forceinline__ void mma16816(float* c, const unsigned a[4], unsigned b0, unsigned b1) {
    asm volatile("mma.sync.aligned.m16n8k16.row.col.f32.f16.f16.f32 "
        "{%0,%1,%2,%3}, {%4,%5,%6,%7}, {%8,%9}, {%0,%1,%2,%3};"
        : "+f"(c[0]), "+f"(c[1]), "+f"(c[2]), "+f"(c[3])
        : "r"(a[0]), "r"(a[1]), "r"(a[2]), "r"(a[3]), "r"(b0), "r"(b1));
}
// m16n8k8 row.col f16xf16 -> f32
__device__ __forceinline__ void mma1688(float* c, const unsigned a[2], unsigned b) {
    asm volatile("mma.sync.aligned.m16n8k8.row.col.f32.f16.f16.f32 "
        "{%0,%1,%2,%3}, {%4,%5}, {%6}, {%0,%1,%2,%3};"
        : "+f"(c[0]), "+f"(c[1]), "+f"(c[2]), "+f"(c[3])
        : "r"(a[0]), "r"(a[1]), "r"(b));
}
// 4x 8x8 fp16 tiles in one shot; lane provides its assigned row address
__device__ __forceinline__ void ldsm_x4(unsigned r[4], unsigned addr) {
    asm volatile("ldmatrix.sync.aligned.m8n8.x4.shared.b16 {%0,%1,%2,%3}, [%4];"
        : "=r"(r[0]), "=r"(r[1]), "=r"(r[2]), "=r"(r[3]) : "r"(addr));
}
__device__ __forceinline__ unsigned smem_u32(const void* p) {
    unsigned a; asm("{ .reg .u64 t; cvta.to.shared.u64 t,%1; cvt.u32.u64 %0,t; }" : "=r"(a) : "l"(p));
    return a;
}
__device__ __forceinline__ u64 um64(u64 a, u64 b) { return a > b ? a : b; }
__device__ __forceinline__ u64 un64(u64 a, u64 b) { return a < b ? a : b; }

// ---------------- prep: E8 roots only ----------------
__global__ void prep_kernel() {
    int i = blockIdx.x * blockDim.x + threadIdx.x;
    if (i >= 240) return;
    float v[8];
#pragma unroll
    for (int k = 0; k < 8; k++) v[k] = 0.f;
    if (i < 112) {
        int p = i >> 2, sb = i & 3;
        int a = 0, rem = p;
        while (rem >= 7 - a) { rem -= (7 - a); a++; }
        int b = a + 1 + rem;
        v[a] = (sb & 2) ? -1.f : 1.f;
        v[b] = (sb & 1) ? -1.f : 1.f;
    } else {
        int b = (i - 112) << 1;
        if (__popc(b) & 1) b |= 1;
#pragma unroll
        for (int k = 0; k < 8; k++) v[k] = ((b >> k) & 1) ? -0.5f : 0.5f;
    }
#pragma unroll
    for (int k = 0; k < 8; k++) g_roots[i * 8 + k] = v[k];
}

__device__ __forceinline__ float gelu_exact(float x) {
    return 0.5f * x * (1.0f + erff(x * 0.70710678118654752f));
}

// Analytic nearest-E8-root decode, branchless u64 reductions, BIT-EXACT.
// |res| >= 0 -> float bits order as uint. Key = (bits << 3) | idxcode keeps
// full value precision; idxcode = (7-k) for max (ties -> lowest k), k for min.
__device__ __forceinline__ int decode_step(float res[8], float s) {
    float a[8];
    u64 pmax[8], pmin[8];
    int mask = 0;
#pragma unroll
    for (int k = 0; k < 8; k++) {
        a[k] = fabsf(res[k]);
        u64 b = ((u64)__float_as_uint(a[k])) << 3;
        pmax[k] = b | (u64)(7 - k);
        pmin[k] = b | (u64)k;
        mask |= (int)(__float_as_uint(res[k]) >> 31) << k;
    }
    u64 M;
    {
        u64 u01 = um64(pmax[0], pmax[1]), u23 = um64(pmax[2], pmax[3]);
        u64 u45 = um64(pmax[4], pmax[5]), u67 = um64(pmax[6], pmax[7]);
        M = um64(um64(u01, u23), um64(u45, u67));
    }
    int m1 = 7 - (int)(M & 7u);
    u64 M2;
    {
        u64 y0 = (pmax[0] == M) ? 0ull : pmax[0], y1 = (pmax[1] == M) ? 0ull : pmax[1];
        u64 y2 = (pmax[2] == M) ? 0ull : pmax[2], y3 = (pmax[3] == M) ? 0ull : pmax[3];
        u64 y4 = (pmax[4] == M) ? 0ull : pmax[4], y5 = (pmax[5] == M) ? 0ull : pmax[5];
        u64 y6 = (pmax[6] == M) ? 0ull : pmax[6], y7 = (pmax[7] == M) ? 0ull : pmax[7];
        M2 = um64(um64(um64(y0, y1), um64(y2, y3)), um64(um64(y4, y5), um64(y6, y7)));
    }
    int m2 = 7 - (int)(M2 & 7u);
    u64 Mn;
    {
        u64 u01 = un64(pmin[0], pmin[1]), u23 = un64(pmin[2], pmin[3]);
        u64 u45 = un64(pmin[4], pmin[5]), u67 = un64(pmin[6], pmin[7]);
        Mn = un64(un64(u01, u23), un64(u45, u67));
    }
    int km = (int)(Mn & 7u);
    float v1 = __uint_as_float((unsigned)(M >> 3));
    float v2 = __uint_as_float((unsigned)(M2 >> 3));
    float vm = __uint_as_float((unsigned)(Mn >> 3));
    float sum = ((a[0] + a[1]) + (a[2] + a[3])) + ((a[4] + a[5]) + (a[6] + a[7]));
    int par = __popc(mask) & 1;
    float valA = v1 + v2;
    float valB = 0.5f * sum - (par ? vm : 0.f);
    int idx;
    if (valA >= valB) {            // tie -> type A (lower enumeration index)
        int i = (m1 < m2) ? m1 : m2, jj = (m1 < m2) ? m2 : m1;
        int bi = (mask >> i) & 1, bj = (mask >> jj) & 1;
        idx = (7 * i - (i * (i - 1)) / 2 + (jj - i - 1)) * 4 + bi * 2 + bj;
        float di = bi ? -s : s, dj = bj ? -s : s;
#pragma unroll
        for (int k = 0; k < 8; k++) {
            if (k == i)  res[k] -= di;
            if (k == jj) res[k] -= dj;
        }
    } else {
        int bits = par ? (mask ^ (1 << km)) : mask;
        idx = 112 + (bits >> 1);
        float hs = 0.5f * s;
#pragma unroll
        for (int k = 0; k < 8; k++) res[k] -= ((bits >> k) & 1) ? -hs : hs;
    }
    return idx;
}

__global__ __launch_bounds__(TPB, 3) void rcpl_kernel(
    const float* __restrict__ obs,   const float* __restrict__ w1, const float* __restrict__ b1,
    const float* __restrict__ w2,    const float* __restrict__ b2,
    const float* __restrict__ le,    const float* __restrict__ bctl,
    const float* __restrict__ rctl,  const float* __restrict__ bc,
    const float* __restrict__ ld,
    const float* __restrict__ rb1,   const float* __restrict__ rw1,
    const float* __restrict__ rw2,   const float* __restrict__ rb2,
    const float* __restrict__ rgate, float* __restrict__ out, int B)
{
    extern __shared__ __align__(16) char sm[];
    __half*   Wt     = reinterpret_cast<__half*>(sm + OFF_WT);
    float*    outS   = reinterpret_cast<float*>(sm + OFF_WT);   // alias, used after Wt reads finish
    __half*   W1H    = reinterpret_cast<__half*>(sm + OFF_W1H);
    __half*   W2H    = reinterpret_cast<__half*>(sm + OFF_W2H);
    __half*   rootsH = reinterpret_cast<__half*>(sm + OFF_ROOTSH);
    float*    kbcS   = reinterpret_cast<float*>(sm + OFF_KBC);
    float*    w1S    = reinterpret_cast<float*>(sm + OFF_W1);
    float*    w2TS   = reinterpret_cast<float*>(sm + OFF_W2T);
    float*    b1S    = reinterpret_cast<float*>(sm + OFF_B1);
    float*    b2S    = reinterpret_cast<float*>(sm + OFF_B2);
    float*    rb1S   = reinterpret_cast<float*>(sm + OFF_RB1);
    float*    rb2S   = reinterpret_cast<float*>(sm + OFF_RB2);
    float*    qS     = reinterpret_cast<float*>(sm + OFF_QS);

    const float C = 1.0201941611100342f;   // log2(e)/sqrt(2)
    const int tid = threadIdx.x;

    // zero softmax W-table + refine W tables (padding must be 0)
    {
        unsigned* wz = reinterpret_cast<unsigned*>(Wt);
        for (int i = tid; i < (64 * WT_STRIDE) / 2; i += TPB) wz[i] = 0u;
        unsigned* z1 = reinterpret_cast<unsigned*>(W1H);
        unsigned* z2 = reinterpret_cast<unsigned*>(W2H);
        for (int i = tid; i < (64 * RW_STRIDE) / 2; i += TPB) { z1[i] = 0u; z2[i] = 0u; }
    }
    __syncthreads();
    for (int i = tid; i < 240 * 56; i += TPB) {
        int j = i / 56, c = i - j * 56;
        float v = (c < 52) ? le[j * 52 + c] : bctl[j * 4 + (c - 52)];
        Wt[c * WT_STRIDE + j] = __float2half_rn(v);
    }
    for (int i = tid; i < 52 * 52; i += TPB) {
        int n = i / 52, k = i - n * 52;
        W1H[n * RW_STRIDE + k] = __float2half_rn(rw1[i]);
        W2H[n * RW_STRIDE + k] = __float2half_rn(rw2[i]);
    }
    for (int i = tid; i < 1920; i += TPB) rootsH[i] = __float2half_rn(g_roots[i]);  // exact
    for (int i = tid; i < 240;  i += TPB) kbcS[i] = bc[i] + 2.0f * C;
    for (int i = tid; i < 448;  i += TPB) w1S[i] = w1[i];
    for (int i = tid; i < 256;  i += TPB) { int l = i >> 3, j = i & 7; w2TS[i] = w2[j * 32 + l]; }
    for (int i = tid; i < 32;   i += TPB) b1S[i] = b1[i];
    for (int i = tid; i < 8;    i += TPB) b2S[i] = b2[i];
    for (int i = tid; i < 56;   i += TPB) {
        rb1S[i] = (i < 52) ? rb1[i] : 0.f;
        rb2S[i] = (i < 52) ? rb2[i] : 0.f;
    }
    __syncthreads();

    int grow = blockIdx.x * TPB + tid;
    int row = (grow < B) ? grow : (B - 1);

    // ---------------- projection 14 -> 32 -> 8 -> qS ----------------
    {
        float x[14];
        const float2* p0 = reinterpret_cast<const float2*>(obs + (size_t)row * 14);
#pragma unroll
        for (int k = 0; k < 7; k++) { float2 v = p0[k]; x[2 * k] = v.x; x[2 * k + 1] = v.y; }
        float q[8];
#pragma unroll
        for (int j = 0; j < 8; j++) q[j] = b2S[j];
#pragma unroll 2
        for (int l = 0; l < 32; l++) {
            float h = b1S[l];
            const float2* wr = reinterpret_cast<const float2*>(&w1S[l * 14]);
#pragma unroll
            for (int k = 0; k < 7; k++) { float2 w = wr[k]; h = fmaf(x[2 * k], w.x, h); h = fmaf(x[2 * k + 1], w.y, h); }
            float g = gelu_exact(h);
            const float4* wt = reinterpret_cast<const float4*>(&w2TS[l * 8]);
            float4 u0 = wt[0], u1 = wt[1];
            q[0] = fmaf(g, u0.x, q[0]); q[1] = fmaf(g, u0.y, q[1]);
            q[2] = fmaf(g, u0.z, q[2]); q[3] = fmaf(g, u0.w, q[3]);
            q[4] = fmaf(g, u1.x, q[4]); q[5] = fmaf(g, u1.y, q[5]);
            q[6] = fmaf(g, u1.z, q[6]); q[7] = fmaf(g, u1.w, q[7]);
        }
        float n2 = 0.f;
#pragma unroll
        for (int j = 0; j < 8; j++) n2 = fmaf(q[j], q[j], n2);
        float sc = 1.4142135623730951f / fmaxf(sqrtf(n2), 1e-12f);
#pragma unroll
        for (int j = 0; j < 8; j++) qS[tid * 10 + j] = q[j] * sc;
    }
    __syncthreads();

    // ---------------- dot GEMM (m16n8k8) + exp + softmax HMMA, ldmatrix W-frags ----------------
    const int wb = (tid >> 5) << 5;
    const int g  = (tid >> 2) & 7;
    const int tq = tid & 3;
    int R[4] = { wb + g, wb + g + 8, wb + g + 16, wb + g + 24 };

    // ldmatrix lane-constant base addresses: call i covers tiles 4i..4i+3; tile t=(n= t>>1, khalf= t&1)
    unsigned ldsm_base[4];
    {
        unsigned lane = (unsigned)(tid & 31);
        unsigned WtU = smem_u32(Wt);
#pragma unroll
        for (int i = 0; i < 4; i++) {
            unsigned t = 4u * i + (lane >> 3);
            unsigned n = t >> 1, h = t & 1, r = lane & 7;
            ldsm_base[i] = WtU + ((n * 8u + r) * WT_STRIDE + h * 8u) * 2u;
        }
    }

    // dot-GEMM A-fragments: (q*C) hi/lo split
    unsigned dah[2][2], dal[2][2];
#pragma unroll
    for (int m = 0; m < 2; m++) {
        float2 v0 = *reinterpret_cast<const float2*>(&qS[(wb + 16 * m + g) * 10 + 2 * tq]);
        float2 v1 = *reinterpret_cast<const float2*>(&qS[(wb + 16 * m + g + 8) * 10 + 2 * tq]);
        split16(v0.x * C, v0.y * C, dah[m][0], dal[m][0]);
        split16(v1.x * C, v1.y * C, dah[m][1], dal[m][1]);
    }

    float cacc[56];
#pragma unroll
    for (int k = 0; k < 56; k++) cacc[k] = 0.f;
    float sS[4] = {0.f, 0.f, 0.f, 0.f};

#pragma unroll 1
    for (int kt = 0; kt < 15; kt++) {
        // W-fragments first (independent of this iteration's dots -> latency hidden)
        unsigned bW[16];
        unsigned koff = (unsigned)(kt * 32);
        ldsm_x4(&bW[0],  ldsm_base[0] + koff);
        ldsm_x4(&bW[4],  ldsm_base[1] + koff);
        ldsm_x4(&bW[8],  ldsm_base[2] + koff);
        ldsm_x4(&bW[12], ldsm_base[3] + koff);

        int nt0 = 2 * kt, nt1 = 2 * kt + 1;
        unsigned rb0 = *reinterpret_cast<const unsigned*>(&rootsH[(nt0 * 8 + g) * 8 + 2 * tq]);
        unsigned rb1v = *reinterpret_cast<const unsigned*>(&rootsH[(nt1 * 8 + g) * 8 + 2 * tq]);
        float c00[4] = {0.f,0.f,0.f,0.f}, c01[4] = {0.f,0.f,0.f,0.f};
        float c10[4] = {0.f,0.f,0.f,0.f}, c11[4] = {0.f,0.f,0.f,0.f};
        mma1688(c00, dah[0], rb0);  mma1688(c00, dal[0], rb0);
        mma1688(c01, dah[0], rb1v); mma1688(c01, dal[0], rb1v);
        mma1688(c10, dah[1], rb0);  mma1688(c10, dal[1], rb0);
        mma1688(c11, dah[1], rb1v); mma1688(c11, dal[1], rb1v);

        float2 kb0 = *reinterpret_cast<const float2*>(&kbcS[nt0 * 8 + 2 * tq]);
        float2 kb1 = *reinterpret_cast<const float2*>(&kbcS[nt1 * 8 + 2 * tq]);

        float e000 = ex2a(c00[0] - kb0.x), e001 = ex2a(c00[1] - kb0.y);
        float e002 = ex2a(c00[2] - kb0.x), e003 = ex2a(c00[3] - kb0.y);
        float e100 = ex2a(c01[0] - kb1.x), e101 = ex2a(c01[1] - kb1.y);
        float e102 = ex2a(c01[2] - kb1.x), e103 = ex2a(c01[3] - kb1.y);
        float e200 = ex2a(c10[0] - kb0.x), e201 = ex2a(c10[1] - kb0.y);
        float e202 = ex2a(c10[2] - kb0.x), e203 = ex2a(c10[3] - kb0.y);
        float e300 = ex2a(c11[0] - kb1.x), e301 = ex2a(c11[1] - kb1.y);
        float e302 = ex2a(c11[2] - kb1.x), e303 = ex2a(c11[3] - kb1.y);

        sS[0] += (e000 + e001) + (e100 + e101);
        sS[1] += (e002 + e003) + (e102 + e103);
        sS[2] += (e200 + e201) + (e300 + e301);
        sS[3] += (e202 + e203) + (e302 + e303);

        unsigned aT0[4], aT1[4];
        aT0[0] = pk16(e000, e001); aT0[1] = pk16(e002, e003);
        aT0[2] = pk16(e100, e101); aT0[3] = pk16(e102, e103);
        aT1[0] = pk16(e200, e201); aT1[1] = pk16(e202, e203);
        aT1[2] = pk16(e300, e301); aT1[3] = pk16(e302, e303);

#pragma unroll
        for (int n = 0; n < 7; n++) {
            mma16816(&cacc[n * 8],     aT0, bW[2 * n], bW[2 * n + 1]);
            mma16816(&cacc[n * 8 + 4], aT1, bW[2 * n], bW[2 * n + 1]);
        }
    }

#pragma unroll
    for (int r = 0; r < 4; r++) {
        sS[r] += __shfl_xor_sync(0xFFFFFFFFu, sS[r], 1);
        sS[r] += __shfl_xor_sync(0xFFFFFFFFu, sS[r], 2);
        sS[r] = 1.0f / sS[r];
    }

    // all MMA reads of Wt done -> reuse region as outS
    __syncthreads();
#pragma unroll
    for (int n = 0; n < 7; n++) {
#pragma unroll
        for (int tl = 0; tl < 2; tl++) {
            const float* c = &cacc[n * 8 + tl * 4];
            int ra = tl * 2, rb = tl * 2 + 1;
            float2* pa = reinterpret_cast<float2*>(&outS[R[ra] * 60 + n * 8 + 2 * tq]);
            float2* pb = reinterpret_cast<float2*>(&outS[R[rb] * 60 + n * 8 + 2 * tq]);
            *pa = make_float2(c[0] * sS[ra], c[1] * sS[ra]);
            *pb = make_float2(c[2] * sS[rb], c[3] * sS[rb]);
        }
    }
    __syncthreads();

    // ---------------- residual E8 decode + level gathers (fp32 exact, own row) ----------------
    {
        u64 acc[28];
        const u64* op = reinterpret_cast<const u64*>(&outS[tid * 60]);
#pragma unroll
        for (int k = 0; k < 28; k++) acc[k] = op[k];

        float invd = expf(-ld[0]);
        float res[8];
        const u64* qp_ = reinterpret_cast<const u64*>(&qS[tid * 10]);
#pragma unroll
        for (int k = 0; k < 4; k++) upk(res[2 * k], res[2 * k + 1], qp_[k]);
        float s = 2.f, gg = 1.f;
#pragma unroll
        for (int lev = 0; lev < 8; lev++) {
            int idx = decode_step(res, s);
            if (lev > 0) {
                u64 gb = pk(gg, gg);
                const ulonglong2* ep = reinterpret_cast<const ulonglong2*>(le + ((size_t)lev * 240 + idx) * 52);
#pragma unroll
                for (int k = 0; k < 13; k++) {
                    ulonglong2 w = __ldg(&ep[k]);
                    acc[2 * k]     = f2fma(gb, w.x, acc[2 * k]);
                    acc[2 * k + 1] = f2fma(gb, w.y, acc[2 * k + 1]);
                }
                ulonglong2 cv = __ldg(reinterpret_cast<const ulonglong2*>(rctl + ((size_t)(lev - 1) * 240 + idx) * 4));
                acc[26] = f2fma(gb, cv.x, acc[26]); acc[27] = f2fma(gb, cv.y, acc[27]);
            }
            s *= invd; gg *= invd;
        }
        u64* ow = reinterpret_cast<u64*>(&outS[tid * 60]);
#pragma unroll
        for (int k = 0; k < 28; k++) ow[k] = acc[k];
    }
    __syncwarp();

    // ---------------- gated refine MLP via HMMA (warp-local rows) ----------------
    {
        const unsigned* W1Hu = reinterpret_cast<const unsigned*>(W1H);
        const unsigned* W2Hu = reinterpret_cast<const unsigned*>(W2H);
        float gate = 1.0f / (1.0f + expf(-rgate[0]));

#pragma unroll 1
        for (int rt = 0; rt < 2; rt++) {
            int ra = wb + 16 * rt + g, rbr = ra + 8;

            unsigned A1h[16], A1l[16];
#pragma unroll
            for (int kt = 0; kt < 4; kt++) {
                int k0 = kt * 16 + 2 * tq;
#pragma unroll
                for (int e = 0; e < 4; e++) {
                    int rr = (e & 1) ? rbr : ra;
                    int kk = k0 + ((e >> 1) << 3);
                    float2 v = (kk < 52) ? *reinterpret_cast<const float2*>(&outS[rr * 60 + kk])
                                         : make_float2(0.f, 0.f);
                    split16(v.x, v.y, A1h[kt * 4 + e], A1l[kt * 4 + e]);
                }
            }

            float C2[28];
#pragma unroll
            for (int k = 0; k < 28; k++) C2[k] = 0.f;

#pragma unroll 1
            for (int kt2 = 0; kt2 < 4; kt2++) {
                float c1[2][4] = {{0.f,0.f,0.f,0.f},{0.f,0.f,0.f,0.f}};
#pragma unroll
                for (int kt = 0; kt < 4; kt++) {
#pragma unroll
                    for (int h2 = 0; h2 < 2; h2++) {
                        unsigned bi = (unsigned)(((2 * kt2 + h2) * 8 + g) * (RW_STRIDE / 2) + kt * 8 + tq);
                        unsigned b0 = W1Hu[bi], b1v = W1Hu[bi + 4];
                        mma16816(c1[h2], &A1h[kt * 4], b0, b1v);
                        mma16816(c1[h2], &A1l[kt * 4], b0, b1v);
                    }
                }
                unsigned a2h[4], a2l[4];
#pragma unroll
                for (int h2 = 0; h2 < 2; h2++) {
                    int cb = (2 * kt2 + h2) * 8 + 2 * tq;
                    float2 rbp = *reinterpret_cast<const float2*>(&rb1S[cb]);
                    float g0 = gelu_exact(c1[h2][0] + rbp.x);
                    float g1 = gelu_exact(c1[h2][1] + rbp.y);
                    float g2 = gelu_exact(c1[h2][2] + rbp.x);
                    float g3 = gelu_exact(c1[h2][3] + rbp.y);
                    if (h2 == 0) { split16(g0, g1, a2h[0], a2l[0]); split16(g2, g3, a2h[1], a2l[1]); }
                    else         { split16(g0, g1, a2h[2], a2l[2]); split16(g2, g3, a2h[3], a2l[3]); }
                }
#pragma unroll
                for (int nt2 = 0; nt2 < 7; nt2++) {
                    unsigned bi = (unsigned)((nt2 * 8 + g) * (RW_STRIDE / 2) + kt2 * 8 + tq);
                    unsigned b0 = W2Hu[bi], b1v = W2Hu[bi + 4];
                    mma16816(&C2[nt2 * 4], a2h, b0, b1v);
                    mma16816(&C2[nt2 * 4], a2l, b0, b1v);
                }
            }
#pragma unroll
            for (int nt2 = 0; nt2 < 7; nt2++) {
                int c0 = nt2 * 8 + 2 * tq;
                float2 rbp = *reinterpret_cast<const float2*>(&rb2S[c0]);
                float2* pa = reinterpret_cast<float2*>(&outS[ra * 60 + c0]);
                float2 va = *pa;
                va.x = fmaf(gate, C2[nt2 * 4 + 0] + rbp.x, va.x);
                va.y = fmaf(gate, C2[nt2 * 4 + 1] + rbp.y, va.y);
                *pa = va;
                float2* pb = reinterpret_cast<float2*>(&outS[rbr * 60 + c0]);
                float2 vb = *pb;
                vb.x = fmaf(gate, C2[nt2 * 4 + 2] + rbp.x, vb.x);
                vb.y = fmaf(gate, C2[nt2 * 4 + 3] + rbp.y, vb.y);
                *pb = vb;
            }
        }
    }
    __syncwarp();

    // ---------------- final store (own row) ----------------
    if (grow < B) {
        const float4* op = reinterpret_cast<const float4*>(&outS[tid * 60]);
        float4* og = reinterpret_cast<float4*>(out + (size_t)grow * 56);
#pragma unroll
        for (int c4 = 0; c4 < 14; c4++) og[c4] = op[c4];
    }
}

extern "C" void kernel_launch(void* const* d_in, const int* in_sizes, int n_in,
                              void* d_out, int out_size) {
    const float* obs   = (const float*)d_in[0];
    const float* w1    = (const float*)d_in[1];
    const float* b1    = (const float*)d_in[2];
    const float* w2    = (const float*)d_in[3];
    const float* b2    = (const float*)d_in[4];
    const float* le    = (const float*)d_in[5];
    const float* bctl  = (const float*)d_in[6];
    const float* rctl  = (const float*)d_in[7];
    const float* bc    = (const float*)d_in[8];
    const float* ld    = (const float*)d_in[9];
    const float* rw1   = (const float*)d_in[10];
    const float* rb1   = (const float*)d_in[11];
    const float* rw2   = (const float*)d_in[12];
    const float* rb2   = (const float*)d_in[13];
    const float* rgate = (const float*)d_in[14];
    float* out = (float*)d_out;

    int B = in_sizes[0] / 14;

    prep_kernel<<<1, 256>>>();

    cudaFuncSetAttribute(rcpl_kernel, cudaFuncAttributeMaxDynamicSharedMemorySize, SMEM_REQ);
    int blocks = (B + TPB - 1) / TPB;
    rcpl_kernel<<<blocks, TPB, SMEM_REQ>>>(
        obs, w1, b1, w2, b2, le, bctl, rctl, bc, ld, rb1, rw1, rw2, rb2, rgate, out, B);
}

// round 17
// speedup vs baseline: 1.6435x; 1.0455x over previous
#include <cuda_runtime.h>
#include <cuda_fp16.h>
#include <math.h>

#define TPB 128

__device__ __align__(16) float g_roots[240 * 8];

// ---------------- dynamic smem layout (byte offsets, 16B-aligned base) ----------------
#define OFF_WT     0        // fp16 Wt softmax [64][248] = 31744 B; aliased by outS fp32 [128][60]
#define WT_STRIDE  248
#define OFF_W1H    31744    // fp16 refine W1 [64][72] = 9216 B (zero-padded)
#define OFF_W2H    40960    // fp16 refine W2 [64][72] = 9216 B
#define RW_STRIDE  72
#define OFF_ROOTSH 50176    // fp16 roots [240][8] = 3840 B (exact in fp16)
#define OFF_KBC    54016    // 240 f
#define OFF_W1     54976    // 448 f
#define OFF_W2T    56768    // 256 f
#define OFF_B1     57792    // 32 f
#define OFF_B2     57920    // 8 f
#define OFF_RB1    57952    // 56 f (padded)
#define OFF_RB2    58176    // 56 f (padded)
#define OFF_QS     58400    // 128 x 10 f
#define SMEM_REQ   63520

typedef unsigned long long u64;

// ---------------- PTX helpers ----------------
__device__ __forceinline__ u64 pk(float x, float y) {
    u64 r; asm("mov.b64 %0,{%1,%2};" : "=l"(r) : "f"(x), "f"(y)); return r;
}
__device__ __forceinline__ void upk(float& x, float& y, u64 v) {
    asm("mov.b64 {%0,%1},%2;" : "=f"(x), "=f"(y) : "l"(v));
}
__device__ __forceinline__ u64 f2fma(u64 a, u64 b, u64 c) {
    u64 d; asm("fma.rn.f32x2 %0,%1,%2,%3;" : "=l"(d) : "l"(a), "l"(b), "l"(c)); return d;
}
__device__ __forceinline__ float ex2a(float x) {
    float y; asm("ex2.approx.ftz.f32 %0,%1;" : "=f"(y) : "f"(x)); return y;
}
// f16x2 with `lo` in the low half
__device__ __forceinline__ unsigned pk16(float lo, float hi) {
    unsigned d; asm("cvt.rn.f16x2.f32 %0,%1,%2;" : "=r"(d) : "f"(hi), "f"(lo)); return d;
}
// hi/lo split for fp32-accurate fp16 MMA (A-side correction)
__device__ __forceinline__ void split16(float x, float y, unsigned& hi, unsigned& lo) {
    hi = pk16(x, y);
    __half2 h = *reinterpret_cast<__half2*>(&hi);
    float2 f = __half22float2(h);
    lo = pk16(x - f.x, y - f.y);
}
// m16n8k16 row.col f16xf16 -> f32
__device__ __forceinline__ void mma16816(float* c, const unsigned a[4], unsigned b0, unsigned b1) {
    asm volatile("mma.sync.aligned.m16n8k16.row.col.f32.f16.f16.f32 "
        "{%0,%1,%2,%3}, {%4,%5,%6,%7}, {%8,%9}, {%0,%1,%2,%3};"
        : "+f"(c[0]), "+f"(c[1]), "+f"(c[2]), "+f"(c[3])
        : "r"(a[0]), "r"(a[1]), "r"(a[2]), "r"(a[3]), "r"(b0), "r"(b1));
}
// m16n8k8 row.col f16xf16 -> f32
__device__ __forceinline__ void mma1688(float* c, const unsigned a[2], unsigned b) {
    asm volatile("mma.sync.aligned.m16n8k8.row.col.f32.f16.f16.f32 "
        "{%0,%1,%2,%3}, {%4,%5}, {%6}, {%0,%1,%2,%3};"
        : "+f"(c[0]), "+f"(c[1]), "+f"(c[2]), "+f"(c[3])
        : "r"(a[0]), "r"(a[1]), "r"(b));
}
// 4x 8x8 fp16 tiles in one shot; lane provides its assigned row address
__device__ __forceinline__ void ldsm_x4(unsigned r[4], unsigned addr) {
    asm volatile("ldmatrix.sync.aligned.m8n8.x4.shared.b16 {%0,%1,%2,%3}, [%4];"
        : "=r"(r[0]), "=r"(r[1]), "=r"(r[2]), "=r"(r[3]) : "r"(addr));
}
__device__ __forceinline__ unsigned smem_u32(const void* p) {
    unsigned a; asm("{ .reg .u64 t; cvta.to.shared.u64 t,%1; cvt.u32.u64 %0,t; }" : "=r"(a) : "l"(p));
    return a;
}
__device__ __forceinline__ u64 um64(u64 a, u64 b) { return a > b ? a : b; }
__device__ __forceinline__ u64 un64(u64 a, u64 b) { return a < b ? a : b; }

// ---------------- prep: E8 roots only ----------------
__global__ void prep_kernel() {
    int i = blockIdx.x * blockDim.x + threadIdx.x;
    if (i >= 240) return;
    float v[8];
#pragma unroll
    for (int k = 0; k < 8; k++) v[k] = 0.f;
    if (i < 112) {
        int p = i >> 2, sb = i & 3;
        int a = 0, rem = p;
        while (rem >= 7 - a) { rem -= (7 - a); a++; }
        int b = a + 1 + rem;
        v[a] = (sb & 2) ? -1.f : 1.f;
        v[b] = (sb & 1) ? -1.f : 1.f;
    } else {
        int b = (i - 112) << 1;
        if (__popc(b) & 1) b |= 1;
#pragma unroll
        for (int k = 0; k < 8; k++) v[k] = ((b >> k) & 1) ? -0.5f : 0.5f;
    }
#pragma unroll
    for (int k = 0; k < 8; k++) g_roots[i * 8 + k] = v[k];
}

__device__ __forceinline__ float gelu_exact(float x) {
    return 0.5f * x * (1.0f + erff(x * 0.70710678118654752f));
}

// Analytic nearest-E8-root decode, branchless u64 reductions, BIT-EXACT.
__device__ __forceinline__ int decode_step(float res[8], float s) {
    float a[8];
    u64 pmax[8], pmin[8];
    int mask = 0;
#pragma unroll
    for (int k = 0; k < 8; k++) {
        a[k] = fabsf(res[k]);
        u64 b = ((u64)__float_as_uint(a[k])) << 3;
        pmax[k] = b | (u64)(7 - k);
        pmin[k] = b | (u64)k;
        mask |= (int)(__float_as_uint(res[k]) >> 31) << k;
    }
    u64 M;
    {
        u64 u01 = um64(pmax[0], pmax[1]), u23 = um64(pmax[2], pmax[3]);
        u64 u45 = um64(pmax[4], pmax[5]), u67 = um64(pmax[6], pmax[7]);
        M = um64(um64(u01, u23), um64(u45, u67));
    }
    int m1 = 7 - (int)(M & 7u);
    u64 M2;
    {
        u64 y0 = (pmax[0] == M) ? 0ull : pmax[0], y1 = (pmax[1] == M) ? 0ull : pmax[1];
        u64 y2 = (pmax[2] == M) ? 0ull : pmax[2], y3 = (pmax[3] == M) ? 0ull : pmax[3];
        u64 y4 = (pmax[4] == M) ? 0ull : pmax[4], y5 = (pmax[5] == M) ? 0ull : pmax[5];
        u64 y6 = (pmax[6] == M) ? 0ull : pmax[6], y7 = (pmax[7] == M) ? 0ull : pmax[7];
        M2 = um64(um64(um64(y0, y1), um64(y2, y3)), um64(um64(y4, y5), um64(y6, y7)));
    }
    int m2 = 7 - (int)(M2 & 7u);
    u64 Mn;
    {
        u64 u01 = un64(pmin[0], pmin[1]), u23 = un64(pmin[2], pmin[3]);
        u64 u45 = un64(pmin[4], pmin[5]), u67 = un64(pmin[6], pmin[7]);
        Mn = un64(un64(u01, u23), un64(u45, u67));
    }
    int km = (int)(Mn & 7u);
    float v1 = __uint_as_float((unsigned)(M >> 3));
    float v2 = __uint_as_float((unsigned)(M2 >> 3));
    float vm = __uint_as_float((unsigned)(Mn >> 3));
    float sum = ((a[0] + a[1]) + (a[2] + a[3])) + ((a[4] + a[5]) + (a[6] + a[7]));
    int par = __popc(mask) & 1;
    float valA = v1 + v2;
    float valB = 0.5f * sum - (par ? vm : 0.f);
    int idx;
    if (valA >= valB) {            // tie -> type A (lower enumeration index)
        int i = (m1 < m2) ? m1 : m2, jj = (m1 < m2) ? m2 : m1;
        int bi = (mask >> i) & 1, bj = (mask >> jj) & 1;
        idx = (7 * i - (i * (i - 1)) / 2 + (jj - i - 1)) * 4 + bi * 2 + bj;
        float di = bi ? -s : s, dj = bj ? -s : s;
#pragma unroll
        for (int k = 0; k < 8; k++) {
            if (k == i)  res[k] -= di;
            if (k == jj) res[k] -= dj;
        }
    } else {
        int bits = par ? (mask ^ (1 << km)) : mask;
        idx = 112 + (bits >> 1);
        float hs = 0.5f * s;
#pragma unroll
        for (int k = 0; k < 8; k++) res[k] -= ((bits >> k) & 1) ? -hs : hs;
    }
    return idx;
}

__global__ __launch_bounds__(TPB, 3) void rcpl_kernel(
    const float* __restrict__ obs,   const float* __restrict__ w1, const float* __restrict__ b1,
    const float* __restrict__ w2,    const float* __restrict__ b2,
    const float* __restrict__ le,    const float* __restrict__ bctl,
    const float* __restrict__ rctl,  const float* __restrict__ bc,
    const float* __restrict__ ld,
    const float* __restrict__ rb1,   const float* __restrict__ rw1,
    const float* __restrict__ rw2,   const float* __restrict__ rb2,
    const float* __restrict__ rgate, float* __restrict__ out, int B)
{
    extern __shared__ __align__(16) char sm[];
    __half*   Wt     = reinterpret_cast<__half*>(sm + OFF_WT);
    float*    outS   = reinterpret_cast<float*>(sm + OFF_WT);   // alias, used after Wt reads finish
    __half*   W1H    = reinterpret_cast<__half*>(sm + OFF_W1H);
    __half*   W2H    = reinterpret_cast<__half*>(sm + OFF_W2H);
    __half*   rootsH = reinterpret_cast<__half*>(sm + OFF_ROOTSH);
    float*    kbcS   = reinterpret_cast<float*>(sm + OFF_KBC);
    float*    w1S    = reinterpret_cast<float*>(sm + OFF_W1);
    float*    w2TS   = reinterpret_cast<float*>(sm + OFF_W2T);
    float*    b1S    = reinterpret_cast<float*>(sm + OFF_B1);
    float*    b2S    = reinterpret_cast<float*>(sm + OFF_B2);
    float*    rb1S   = reinterpret_cast<float*>(sm + OFF_RB1);
    float*    rb2S   = reinterpret_cast<float*>(sm + OFF_RB2);
    float*    qS     = reinterpret_cast<float*>(sm + OFF_QS);

    const float C = 1.0201941611100342f;   // log2(e)/sqrt(2)
    const int tid = threadIdx.x;

    // zero softmax W-table + refine W tables (padding must be 0)
    {
        unsigned* wz = reinterpret_cast<unsigned*>(Wt);
        for (int i = tid; i < (64 * WT_STRIDE) / 2; i += TPB) wz[i] = 0u;
        unsigned* z1 = reinterpret_cast<unsigned*>(W1H);
        unsigned* z2 = reinterpret_cast<unsigned*>(W2H);
        for (int i = tid; i < (64 * RW_STRIDE) / 2; i += TPB) { z1[i] = 0u; z2[i] = 0u; }
    }
    __syncthreads();
    for (int i = tid; i < 240 * 56; i += TPB) {
        int j = i / 56, c = i - j * 56;
        float v = (c < 52) ? le[j * 52 + c] : bctl[j * 4 + (c - 52)];
        Wt[c * WT_STRIDE + j] = __float2half_rn(v);
    }
    for (int i = tid; i < 52 * 52; i += TPB) {
        int n = i / 52, k = i - n * 52;
        W1H[n * RW_STRIDE + k] = __float2half_rn(rw1[i]);
        W2H[n * RW_STRIDE + k] = __float2half_rn(rw2[i]);
    }
    for (int i = tid; i < 1920; i += TPB) rootsH[i] = __float2half_rn(g_roots[i]);  // exact
    for (int i = tid; i < 240;  i += TPB) kbcS[i] = bc[i] + 2.0f * C;
    for (int i = tid; i < 448;  i += TPB) w1S[i] = w1[i];
    for (int i = tid; i < 256;  i += TPB) { int l = i >> 3, j = i & 7; w2TS[i] = w2[j * 32 + l]; }
    for (int i = tid; i < 32;   i += TPB) b1S[i] = b1[i];
    for (int i = tid; i < 8;    i += TPB) b2S[i] = b2[i];
    for (int i = tid; i < 56;   i += TPB) {
        rb1S[i] = (i < 52) ? rb1[i] : 0.f;
        rb2S[i] = (i < 52) ? rb2[i] : 0.f;
    }
    __syncthreads();

    int grow = blockIdx.x * TPB + tid;
    int row = (grow < B) ? grow : (B - 1);
    const int gb0 = blockIdx.x * TPB;          // block's first global row

    // ---------------- projection 14 -> 32 -> 8 -> qS ----------------
    {
        float x[14];
        const float2* p0 = reinterpret_cast<const float2*>(obs + (size_t)row * 14);
#pragma unroll
        for (int k = 0; k < 7; k++) { float2 v = p0[k]; x[2 * k] = v.x; x[2 * k + 1] = v.y; }
        float q[8];
#pragma unroll
        for (int j = 0; j < 8; j++) q[j] = b2S[j];
#pragma unroll 2
        for (int l = 0; l < 32; l++) {
            float h = b1S[l];
            const float2* wr = reinterpret_cast<const float2*>(&w1S[l * 14]);
#pragma unroll
            for (int k = 0; k < 7; k++) { float2 w = wr[k]; h = fmaf(x[2 * k], w.x, h); h = fmaf(x[2 * k + 1], w.y, h); }
            float g = gelu_exact(h);
            const float4* wt = reinterpret_cast<const float4*>(&w2TS[l * 8]);
            float4 u0 = wt[0], u1 = wt[1];
            q[0] = fmaf(g, u0.x, q[0]); q[1] = fmaf(g, u0.y, q[1]);
            q[2] = fmaf(g, u0.z, q[2]); q[3] = fmaf(g, u0.w, q[3]);
            q[4] = fmaf(g, u1.x, q[4]); q[5] = fmaf(g, u1.y, q[5]);
            q[6] = fmaf(g, u1.z, q[6]); q[7] = fmaf(g, u1.w, q[7]);
        }
        float n2 = 0.f;
#pragma unroll
        for (int j = 0; j < 8; j++) n2 = fmaf(q[j], q[j], n2);
        float sc = 1.4142135623730951f / fmaxf(sqrtf(n2), 1e-12f);
#pragma unroll
        for (int j = 0; j < 8; j++) qS[tid * 10 + j] = q[j] * sc;
    }
    __syncthreads();

    // ---------------- dot GEMM (m16n8k8) + exp + softmax HMMA, ldmatrix W-frags ----------------
    const int wb = (tid >> 5) << 5;
    const int g  = (tid >> 2) & 7;
    const int tq = tid & 3;
    int R[4] = { wb + g, wb + g + 8, wb + g + 16, wb + g + 24 };

    unsigned ldsm_base[4];
    {
        unsigned lane = (unsigned)(tid & 31);
        unsigned WtU = smem_u32(Wt);
#pragma unroll
        for (int i = 0; i < 4; i++) {
            unsigned t = 4u * i + (lane >> 3);
            unsigned n = t >> 1, h = t & 1, r = lane & 7;
            ldsm_base[i] = WtU + ((n * 8u + r) * WT_STRIDE + h * 8u) * 2u;
        }
    }

    unsigned dah[2][2], dal[2][2];
#pragma unroll
    for (int m = 0; m < 2; m++) {
        float2 v0 = *reinterpret_cast<const float2*>(&qS[(wb + 16 * m + g) * 10 + 2 * tq]);
        float2 v1 = *reinterpret_cast<const float2*>(&qS[(wb + 16 * m + g + 8) * 10 + 2 * tq]);
        split16(v0.x * C, v0.y * C, dah[m][0], dal[m][0]);
        split16(v1.x * C, v1.y * C, dah[m][1], dal[m][1]);
    }

    float cacc[56];
#pragma unroll
    for (int k = 0; k < 56; k++) cacc[k] = 0.f;
    float sS[4] = {0.f, 0.f, 0.f, 0.f};

#pragma unroll 1
    for (int kt = 0; kt < 15; kt++) {
        unsigned bW[16];
        unsigned koff = (unsigned)(kt * 32);
        ldsm_x4(&bW[0],  ldsm_base[0] + koff);
        ldsm_x4(&bW[4],  ldsm_base[1] + koff);
        ldsm_x4(&bW[8],  ldsm_base[2] + koff);
        ldsm_x4(&bW[12], ldsm_base[3] + koff);

        int nt0 = 2 * kt, nt1 = 2 * kt + 1;
        unsigned rb0 = *reinterpret_cast<const unsigned*>(&rootsH[(nt0 * 8 + g) * 8 + 2 * tq]);
        unsigned rb1v = *reinterpret_cast<const unsigned*>(&rootsH[(nt1 * 8 + g) * 8 + 2 * tq]);
        float c00[4] = {0.f,0.f,0.f,0.f}, c01[4] = {0.f,0.f,0.f,0.f};
        float c10[4] = {0.f,0.f,0.f,0.f}, c11[4] = {0.f,0.f,0.f,0.f};
        mma1688(c00, dah[0], rb0);  mma1688(c00, dal[0], rb0);
        mma1688(c01, dah[0], rb1v); mma1688(c01, dal[0], rb1v);
        mma1688(c10, dah[1], rb0);  mma1688(c10, dal[1], rb0);
        mma1688(c11, dah[1], rb1v); mma1688(c11, dal[1], rb1v);

        float2 kb0 = *reinterpret_cast<const float2*>(&kbcS[nt0 * 8 + 2 * tq]);
        float2 kb1 = *reinterpret_cast<const float2*>(&kbcS[nt1 * 8 + 2 * tq]);

        float e000 = ex2a(c00[0] - kb0.x), e001 = ex2a(c00[1] - kb0.y);
        float e002 = ex2a(c00[2] - kb0.x), e003 = ex2a(c00[3] - kb0.y);
        float e100 = ex2a(c01[0] - kb1.x), e101 = ex2a(c01[1] - kb1.y);
        float e102 = ex2a(c01[2] - kb1.x), e103 = ex2a(c01[3] - kb1.y);
        float e200 = ex2a(c10[0] - kb0.x), e201 = ex2a(c10[1] - kb0.y);
        float e202 = ex2a(c10[2] - kb0.x), e203 = ex2a(c10[3] - kb0.y);
        float e300 = ex2a(c11[0] - kb1.x), e301 = ex2a(c11[1] - kb1.y);
        float e302 = ex2a(c11[2] - kb1.x), e303 = ex2a(c11[3] - kb1.y);

        sS[0] += (e000 + e001) + (e100 + e101);
        sS[1] += (e002 + e003) + (e102 + e103);
        sS[2] += (e200 + e201) + (e300 + e301);
        sS[3] += (e202 + e203) + (e302 + e303);

        unsigned aT0[4], aT1[4];
        aT0[0] = pk16(e000, e001); aT0[1] = pk16(e002, e003);
        aT0[2] = pk16(e100, e101); aT0[3] = pk16(e102, e103);
        aT1[0] = pk16(e200, e201); aT1[1] = pk16(e202, e203);
        aT1[2] = pk16(e300, e301); aT1[3] = pk16(e302, e303);

#pragma unroll
        for (int n = 0; n < 7; n++) {
            mma16816(&cacc[n * 8],     aT0, bW[2 * n], bW[2 * n + 1]);
            mma16816(&cacc[n * 8 + 4], aT1, bW[2 * n], bW[2 * n + 1]);
        }
    }

#pragma unroll
    for (int r = 0; r < 4; r++) {
        sS[r] += __shfl_xor_sync(0xFFFFFFFFu, sS[r], 1);
        sS[r] += __shfl_xor_sync(0xFFFFFFFFu, sS[r], 2);
        sS[r] = 1.0f / sS[r];
    }

    // all MMA reads of Wt done -> reuse region as outS
    __syncthreads();
#pragma unroll
    for (int n = 0; n < 7; n++) {
#pragma unroll
        for (int tl = 0; tl < 2; tl++) {
            const float* c = &cacc[n * 8 + tl * 4];
            int ra = tl * 2, rb = tl * 2 + 1;
            float2* pa = reinterpret_cast<float2*>(&outS[R[ra] * 60 + n * 8 + 2 * tq]);
            float2* pb = reinterpret_cast<float2*>(&outS[R[rb] * 60 + n * 8 + 2 * tq]);
            *pa = make_float2(c[0] * sS[ra], c[1] * sS[ra]);
            *pb = make_float2(c[2] * sS[rb], c[3] * sS[rb]);
        }
    }
    __syncthreads();

    // ---------------- residual E8 decode + level gathers (fp32 exact, own row) ----------------
    {
        u64 acc[28];
        const u64* op = reinterpret_cast<const u64*>(&outS[tid * 60]);
#pragma unroll
        for (int k = 0; k < 28; k++) acc[k] = op[k];

        float invd = expf(-ld[0]);
        float res[8];
        const u64* qp_ = reinterpret_cast<const u64*>(&qS[tid * 10]);
#pragma unroll
        for (int k = 0; k < 4; k++) upk(res[2 * k], res[2 * k + 1], qp_[k]);
        float s = 2.f, gg = 1.f;
#pragma unroll
        for (int lev = 0; lev < 8; lev++) {
            int idx = decode_step(res, s);
            if (lev > 0) {
                u64 gb = pk(gg, gg);
                const ulonglong2* ep = reinterpret_cast<const ulonglong2*>(le + ((size_t)lev * 240 + idx) * 52);
#pragma unroll
                for (int k = 0; k < 13; k++) {
                    ulonglong2 w = __ldg(&ep[k]);
                    acc[2 * k]     = f2fma(gb, w.x, acc[2 * k]);
                    acc[2 * k + 1] = f2fma(gb, w.y, acc[2 * k + 1]);
                }
                ulonglong2 cv = __ldg(reinterpret_cast<const ulonglong2*>(rctl + ((size_t)(lev - 1) * 240 + idx) * 4));
                acc[26] = f2fma(gb, cv.x, acc[26]); acc[27] = f2fma(gb, cv.y, acc[27]);
            }
            s *= invd; gg *= invd;
        }
        u64* ow = reinterpret_cast<u64*>(&outS[tid * 60]);
#pragma unroll
        for (int k = 0; k < 28; k++) ow[k] = acc[k];
    }
    __syncwarp();

    // ---------------- gated refine MLP via HMMA; epilogue stores direct to gmem ----------------
    {
        const unsigned* W1Hu = reinterpret_cast<const unsigned*>(W1H);
        const unsigned* W2Hu = reinterpret_cast<const unsigned*>(W2H);
        float gate = 1.0f / (1.0f + expf(-rgate[0]));

#pragma unroll 1
        for (int rt = 0; rt < 2; rt++) {
            int ra = wb + 16 * rt + g, rbr = ra + 8;

            unsigned A1h[16], A1l[16];
#pragma unroll
            for (int kt = 0; kt < 4; kt++) {
                int k0 = kt * 16 + 2 * tq;
#pragma unroll
                for (int e = 0; e < 4; e++) {
                    int rr = (e & 1) ? rbr : ra;
                    int kk = k0 + ((e >> 1) << 3);
                    float2 v = (kk < 52) ? *reinterpret_cast<const float2*>(&outS[rr * 60 + kk])
                                         : make_float2(0.f, 0.f);
                    split16(v.x, v.y, A1h[kt * 4 + e], A1l[kt * 4 + e]);
                }
            }

            float C2[28];
#pragma unroll
            for (int k = 0; k < 28; k++) C2[k] = 0.f;

#pragma unroll 1
            for (int kt2 = 0; kt2 < 4; kt2++) {
                float c1[2][4] = {{0.f,0.f,0.f,0.f},{0.f,0.f,0.f,0.f}};
#pragma unroll
                for (int kt = 0; kt < 4; kt++) {
#pragma unroll
                    for (int h2 = 0; h2 < 2; h2++) {
                        unsigned bi = (unsigned)(((2 * kt2 + h2) * 8 + g) * (RW_STRIDE / 2) + kt * 8 + tq);
                        unsigned b0 = W1Hu[bi], b1v = W1Hu[bi + 4];
                        mma16816(c1[h2], &A1h[kt * 4], b0, b1v);
                        mma16816(c1[h2], &A1l[kt * 4], b0, b1v);
                    }
                }
                // bias + gelu; layer-2 A plain fp16 (gated contribution ~1e-4 rel)
                unsigned a2h[4];
#pragma unroll
                for (int h2 = 0; h2 < 2; h2++) {
                    int cb = (2 * kt2 + h2) * 8 + 2 * tq;
                    float2 rbp = *reinterpret_cast<const float2*>(&rb1S[cb]);
                    float g0 = gelu_exact(c1[h2][0] + rbp.x);
                    float g1 = gelu_exact(c1[h2][1] + rbp.y);
                    float g2 = gelu_exact(c1[h2][2] + rbp.x);
                    float g3 = gelu_exact(c1[h2][3] + rbp.y);
                    if (h2 == 0) { a2h[0] = pk16(g0, g1); a2h[1] = pk16(g2, g3); }
                    else         { a2h[2] = pk16(g0, g1); a2h[3] = pk16(g2, g3); }
                }
#pragma unroll
                for (int nt2 = 0; nt2 < 7; nt2++) {
                    unsigned bi = (unsigned)((nt2 * 8 + g) * (RW_STRIDE / 2) + kt2 * 8 + tq);
                    unsigned b0 = W2Hu[bi], b1v = W2Hu[bi + 4];
                    mma16816(&C2[nt2 * 4], a2h, b0, b1v);
                }
            }
            // epilogue: out = E + gate*(R + rb2), straight to gmem (cols >=52 pass E through)
            int gra = gb0 + ra, grb = gb0 + rbr;
            bool wa = (gra < B), wbv = (grb < B);
#pragma unroll
            for (int nt2 = 0; nt2 < 7; nt2++) {
                int c0 = nt2 * 8 + 2 * tq;
                float2 rbp = *reinterpret_cast<const float2*>(&rb2S[c0]);
                float2 ea = *reinterpret_cast<const float2*>(&outS[ra * 60 + c0]);
                float2 eb = *reinterpret_cast<const float2*>(&outS[rbr * 60 + c0]);
                float2 va, vb;
                va.x = fmaf(gate, C2[nt2 * 4 + 0] + rbp.x, ea.x);
                va.y = fmaf(gate, C2[nt2 * 4 + 1] + rbp.y, ea.y);
                vb.x = fmaf(gate, C2[nt2 * 4 + 2] + rbp.x, eb.x);
                vb.y = fmaf(gate, C2[nt2 * 4 + 3] + rbp.y, eb.y);
                if (wa)  *reinterpret_cast<float2*>(out + (size_t)gra * 56 + c0) = va;
                if (wbv) *reinterpret_cast<float2*>(out + (size_t)grb * 56 + c0) = vb;
            }
        }
    }
}

extern "C" void kernel_launch(void* const* d_in, const int* in_sizes, int n_in,
                              void* d_out, int out_size) {
    const float* obs   = (const float*)d_in[0];
    const float* w1    = (const float*)d_in[1];
    const float* b1    = (const float*)d_in[2];
    const float* w2    = (const float*)d_in[3];
    const float* b2    = (const float*)d_in[4];
    const float* le    = (const float*)d_in[5];
    const float* bctl  = (const float*)d_in[6];
    const float* rctl  = (const float*)d_in[7];
    const float* bc    = (const float*)d_in[8];
    const float* ld    = (const float*)d_in[9];
    const float* rw1   = (const float*)d_in[10];
    const float* rb1   = (const float*)d_in[11];
    const float* rw2   = (const float*)d_in[12];
    const float* rb2   = (const float*)d_in[13];
    const float* rgate = (const float*)d_in[14];
    float* out = (float*)d_out;

    int B = in_sizes[0] / 14;

    prep_kernel<<<1, 256>>>();

    cudaFuncSetAttribute(rcpl_kernel, cudaFuncAttributeMaxDynamicSharedMemorySize, SMEM_REQ);
    int blocks = (B + TPB - 1) / TPB;
    rcpl_kernel<<<blocks, TPB, SMEM_REQ>>>(
        obs, w1, b1, w2, b2, le, bctl, rctl, bc, ld, rb1, rw1, rw2, rb2, rgate, out, B);
}